// round 3
// baseline (speedup 1.0000x reference)
#include <cuda_runtime.h>

#define BB 16
#define SS 4096
#define DD 64
#define NH 8
#define NB 64

// ---------------- scratch (static __device__, allocation-free) ----------------
__device__ int   g_buckets[BB * NH * SS];                 // 2 MB
__device__ int   g_st[BB * NH * SS];                      // 2 MB : sorted pos -> token
__device__ float g_lse[BB * NH * SS];                     // 2 MB : per (b,h,token) logsumexp
__device__ float g_o[(size_t)BB * NH * SS * DD];          // 134 MB : per-round outputs (token layout)

// =============================================================================
// K1: LSH hashing.  rotated[h,t,i] = sum_f qk[b,t,f]*rot[b,f,h,i]
// bucket = argmax over [rotated, -rotated]  (first-occurrence on ties)
// =============================================================================
__global__ __launch_bounds__(256) void hash_kernel(const float* __restrict__ qk,
                                                   const float* __restrict__ rot)
{
    extern __shared__ float rs[];        // [64 f][256 (h*32+i)] = 64 KB
    int b   = blockIdx.y;
    int tid = threadIdx.x;
    const float* rg = rot + (size_t)b * DD * NH * 32;
    #pragma unroll
    for (int k = 0; k < 64; k++) rs[tid + k * 256] = rg[tid + k * 256];
    __syncthreads();

    int t = blockIdx.x * 256 + tid;
    float q[64];
    const float4* qg = (const float4*)(qk + ((size_t)b * SS + t) * DD);
    #pragma unroll
    for (int c = 0; c < 16; c++) {
        float4 u = qg[c];
        q[4*c] = u.x; q[4*c+1] = u.y; q[4*c+2] = u.z; q[4*c+3] = u.w;
    }

    #pragma unroll 1
    for (int h = 0; h < NH; h++) {
        float vals[32];
        #pragma unroll
        for (int i = 0; i < 32; i++) vals[i] = 0.f;
        #pragma unroll
        for (int f = 0; f < 64; f++) {
            float qf = q[f];
            const float4* r4 = (const float4*)(rs + f * 256 + h * 32);
            #pragma unroll
            for (int i4 = 0; i4 < 8; i4++) {
                float4 rv = r4[i4];
                vals[4*i4+0] = fmaf(qf, rv.x, vals[4*i4+0]);
                vals[4*i4+1] = fmaf(qf, rv.y, vals[4*i4+1]);
                vals[4*i4+2] = fmaf(qf, rv.z, vals[4*i4+2]);
                vals[4*i4+3] = fmaf(qf, rv.w, vals[4*i4+3]);
            }
        }
        // argmax over [vals(0..31), -vals(32..63)], first occurrence wins
        float best = vals[0]; int arg = 0;
        #pragma unroll
        for (int i = 1; i < 32; i++) if (vals[i] > best) { best = vals[i]; arg = i; }
        #pragma unroll
        for (int i = 0; i < 32; i++) { float vv = -vals[i]; if (vv > best) { best = vv; arg = 32 + i; } }
        g_buckets[(b * NH + h) * SS + t] = arg;
    }
}

// =============================================================================
// K2: stable counting sort per (b,h): tokens sorted by (bucket, t).
// One block of 128 threads handles 4096 tokens (32 contiguous per thread).
// =============================================================================
__global__ __launch_bounds__(128) void sort_kernel()
{
    __shared__ int hist[64 * 130];       // [bucket][thread], stride 130 (pad)
    __shared__ int base[64];
    int bh  = blockIdx.x;                // b*8+h
    int tid = threadIdx.x;

    for (int k = tid; k < 64 * 130; k += 128) hist[k] = 0;
    __syncthreads();

    const int* bks = g_buckets + bh * SS;
    int myb[32];
    #pragma unroll
    for (int k = 0; k < 32; k++) {
        int bb = bks[tid * 32 + k];
        myb[k] = bb;
        hist[bb * 130 + tid] += 1;       // column tid private to this thread
    }
    __syncthreads();

    if (tid < 64) {                      // per-bucket exclusive scan across threads
        int run = 0;
        for (int j = 0; j < 128; j++) {
            int vv = hist[tid * 130 + j];
            hist[tid * 130 + j] = run;
            run += vv;
        }
        base[tid] = run;
    }
    __syncthreads();
    if (tid == 0) {                      // exclusive scan of bucket totals
        int run = 0;
        for (int u = 0; u < 64; u++) { int vv = base[u]; base[u] = run; run += vv; }
    }
    __syncthreads();

    int* st = g_st + bh * SS;
    #pragma unroll
    for (int k = 0; k < 32; k++) {       // stable scatter (ascending t per thread)
        int bb  = myb[k];
        int off = hist[bb * 130 + tid];
        hist[bb * 130 + tid] = off + 1;
        st[base[bb] + off] = tid * 32 + k;
    }
}

// =============================================================================
// K3: chunked attention.  Block = (b, global chunk c in [0,512)).
// 64 queries x 128 keys (current chunk + previous chunk, wrapping over the
// GLOBAL 512-chunk axis -> cross-hash-round look-back at boundaries).
// Keys are L2-normalized queries; dots_ij = norm_i * 0.125 * (khat_i . khat_j).
// Writes per-round output + lse scattered to token layout (undo_sort fused).
// =============================================================================
#define KNS 68          // K/V row stride (floats), 272 B (16B aligned, conflict-breaking)
#define DTS 133         // dots row stride, 5i+j bijective mod 32 -> conflict-free
#define SM_KN   0
#define SM_VS   (128 * KNS)               // 8704
#define SM_DOTS (2 * 128 * KNS)           // 17408
#define SM_QN   (SM_DOTS + 64 * DTS)      // 25920
#define SM_RED  (SM_QN + 64)              // 25984
#define SM_IDS  (SM_RED + 256)            // 26240
#define ATT_SMEM_FLOATS (SM_IDS + 128)    // 26368 -> 105472 bytes

__global__ __launch_bounds__(256) void attn_kernel(const float* __restrict__ qk,
                                                   const float* __restrict__ vin)
{
    extern __shared__ float sm[];
    float* kn   = sm + SM_KN;
    float* vs   = sm + SM_VS;
    float* dots = sm + SM_DOTS;
    float* qn   = sm + SM_QN;
    float* red  = sm + SM_RED;
    int*   ids  = (int*)(sm + SM_IDS);

    int b   = blockIdx.y;
    int c   = blockIdx.x;                 // global chunk 0..511
    int tid = threadIdx.x;                // 256
    int h   = c >> 6,  lc  = c & 63;
    int pcn = (c + 511) & 511;            // previous chunk (wrap)
    int ph  = pcn >> 6, plc = pcn & 63;

    if (tid < 128) {
        int rr = tid;
        ids[rr] = (rr < 64) ? g_st[(b * NH + h)  * SS + lc  * 64 + rr]
                            : g_st[(b * NH + ph) * SS + plc * 64 + (rr - 64)];
    }
    __syncthreads();

    // ---- gather rows, normalize keys (2 threads per row, shuffle-combined) ----
    {
        int r = tid >> 1, part = tid & 1;
        int t = ids[r];
        const float4* srck = (const float4*)(qk  + ((size_t)b * SS + t) * DD) + part * 8;
        const float4* srcv = (const float4*)(vin + ((size_t)b * SS + t) * DD) + part * 8;
        float4* dstk = (float4*)(kn + r * KNS) + part * 8;
        float4* dstv = (float4*)(vs + r * KNS) + part * 8;
        float4 xr[8];
        float  ssq = 0.f;
        #pragma unroll
        for (int c4 = 0; c4 < 8; c4++) {
            float4 x = srck[c4]; xr[c4] = x;
            ssq += x.x * x.x + x.y * x.y + x.z * x.z + x.w * x.w;
            dstv[c4] = srcv[c4];
        }
        ssq += __shfl_xor_sync(0xffffffffu, ssq, 1);
        float norm = sqrtf(ssq);
        float inv  = 1.0f / fmaxf(norm, 1e-12f);
        #pragma unroll
        for (int c4 = 0; c4 < 8; c4++) {
            float4 x = xr[c4];
            x.x *= inv; x.y *= inv; x.z *= inv; x.w *= inv;
            dstk[c4] = x;
        }
        if (part == 0 && r < 64) qn[r] = norm * 0.125f;   // fold d^-0.5 and |q|
    }
    __syncthreads();

    int i  = tid & 63;                    // query row
    int qq = tid >> 6;                    // quarter (key/d range)
    int ti = ids[i];

    // query in registers: khat_i * (norm_i * 0.125)
    float4 qr[16];
    {
        float sc = qn[i];
        const float4* ks = (const float4*)(kn + i * KNS);
        #pragma unroll
        for (int c4 = 0; c4 < 16; c4++) {
            float4 x = ks[c4];
            x.x *= sc; x.y *= sc; x.z *= sc; x.w *= sc;
            qr[c4] = x;
        }
    }

    // ---- QK^T (this thread: j in [qq*32, qq*32+32)) ----
    int j0 = qq * 32;
    #pragma unroll 1
    for (int j = j0; j < j0 + 32; j++) {
        const float4* kj = (const float4*)(kn + j * KNS);   // broadcast within warp
        float a0 = 0.f, a1 = 0.f, a2 = 0.f, a3 = 0.f;
        #pragma unroll
        for (int c4 = 0; c4 < 16; c4++) {
            float4 kk = kj[c4];
            a0 = fmaf(qr[c4].x, kk.x, a0);
            a1 = fmaf(qr[c4].y, kk.y, a1);
            a2 = fmaf(qr[c4].z, kk.z, a2);
            a3 = fmaf(qr[c4].w, kk.w, a3);
        }
        float acc = (a0 + a1) + (a2 + a3);
        if (ti == ids[j]) acc = -50000.0f;                   // self-attention mask
        dots[i * DTS + j] = acc;
    }
    __syncthreads();

    // ---- softmax with lse (4-way split reduction over j) ----
    float m = -3.4e38f;
    #pragma unroll
    for (int j = 0; j < 32; j++) m = fmaxf(m, dots[i * DTS + j0 + j]);
    red[i * 4 + qq] = m;
    __syncthreads();
    float rm = fmaxf(fmaxf(red[i*4+0], red[i*4+1]), fmaxf(red[i*4+2], red[i*4+3]));
    __syncthreads();
    float sme = 0.f;
    #pragma unroll
    for (int j = 0; j < 32; j++) {
        float p = expf(dots[i * DTS + j0 + j] - rm);
        dots[i * DTS + j0 + j] = p;
        sme += p;
    }
    red[i * 4 + qq] = sme;
    __syncthreads();
    float rsum = (red[i*4+0] + red[i*4+1]) + (red[i*4+2] + red[i*4+3]);
    if (qq == 0) g_lse[(b * NH + h) * SS + ti] = rm + logf(rsum);
    float rinv = 1.0f / rsum;

    // ---- P@V (this thread: d in [qq*16, qq*16+16)) ----
    float4 acc0 = {0,0,0,0}, acc1 = {0,0,0,0}, acc2 = {0,0,0,0}, acc3 = {0,0,0,0};
    #pragma unroll 2
    for (int j = 0; j < 128; j++) {
        float p = dots[i * DTS + j];                          // conflict-free
        const float4* vj = (const float4*)(vs + j * KNS) + qq * 4;  // broadcast
        float4 v0 = vj[0], v1 = vj[1], v2 = vj[2], v3 = vj[3];
        acc0.x = fmaf(p, v0.x, acc0.x); acc0.y = fmaf(p, v0.y, acc0.y);
        acc0.z = fmaf(p, v0.z, acc0.z); acc0.w = fmaf(p, v0.w, acc0.w);
        acc1.x = fmaf(p, v1.x, acc1.x); acc1.y = fmaf(p, v1.y, acc1.y);
        acc1.z = fmaf(p, v1.z, acc1.z); acc1.w = fmaf(p, v1.w, acc1.w);
        acc2.x = fmaf(p, v2.x, acc2.x); acc2.y = fmaf(p, v2.y, acc2.y);
        acc2.z = fmaf(p, v2.z, acc2.z); acc2.w = fmaf(p, v2.w, acc2.w);
        acc3.x = fmaf(p, v3.x, acc3.x); acc3.y = fmaf(p, v3.y, acc3.y);
        acc3.z = fmaf(p, v3.z, acc3.z); acc3.w = fmaf(p, v3.w, acc3.w);
    }
    acc0.x *= rinv; acc0.y *= rinv; acc0.z *= rinv; acc0.w *= rinv;
    acc1.x *= rinv; acc1.y *= rinv; acc1.z *= rinv; acc1.w *= rinv;
    acc2.x *= rinv; acc2.y *= rinv; acc2.z *= rinv; acc2.w *= rinv;
    acc3.x *= rinv; acc3.y *= rinv; acc3.z *= rinv; acc3.w *= rinv;

    float4* dst = (float4*)(g_o + (((size_t)(b * NH + h) * SS + ti) * DD) + qq * 16);
    dst[0] = acc0; dst[1] = acc1; dst[2] = acc2; dst[3] = acc3;
}

// =============================================================================
// K4: combine hash rounds.  16 threads per token (float4 per thread).
// probs = softmax over rounds of lse;  out = sum_h probs_h * o_h
// =============================================================================
__global__ __launch_bounds__(256) void combine_kernel(float* __restrict__ out)
{
    int gid = blockIdx.x * 256 + threadIdx.x;   // B*S*16 = 1,048,576 threads
    int d4  = gid & 15;
    int bt  = gid >> 4;                         // b*4096 + t
    int b   = bt >> 12;
    int t   = bt & 4095;

    float l[8]; float m = -3.4e38f;
    #pragma unroll
    for (int h = 0; h < 8; h++) { l[h] = g_lse[(b * NH + h) * SS + t]; m = fmaxf(m, l[h]); }
    float w[8]; float Z = 0.f;
    #pragma unroll
    for (int h = 0; h < 8; h++) { w[h] = expf(l[h] - m); Z += w[h]; }
    float invZ = 1.0f / Z;

    float4 a = {0,0,0,0};
    #pragma unroll
    for (int h = 0; h < 8; h++) {
        float4 ov = *((const float4*)(g_o + ((size_t)(b * NH + h) * SS + t) * DD) + d4);
        a.x = fmaf(w[h], ov.x, a.x);
        a.y = fmaf(w[h], ov.y, a.y);
        a.z = fmaf(w[h], ov.z, a.z);
        a.w = fmaf(w[h], ov.w, a.w);
    }
    a.x *= invZ; a.y *= invZ; a.z *= invZ; a.w *= invZ;
    ((float4*)out)[(size_t)bt * 16 + d4] = a;
}

// =============================================================================
extern "C" void kernel_launch(void* const* d_in, const int* in_sizes, int n_in,
                              void* d_out, int out_size)
{
    const float* qk  = (const float*)d_in[0];
    const float* v   = (const float*)d_in[1];
    const float* rot = (const float*)d_in[2];
    float* out = (float*)d_out;

    cudaFuncSetAttribute(hash_kernel, cudaFuncAttributeMaxDynamicSharedMemorySize, 65536);
    cudaFuncSetAttribute(attn_kernel, cudaFuncAttributeMaxDynamicSharedMemorySize, ATT_SMEM_FLOATS * 4);

    hash_kernel<<<dim3(SS / 256, BB), 256, 65536>>>(qk, rot);
    sort_kernel<<<BB * NH, 128>>>();
    attn_kernel<<<dim3(512, BB), 256, ATT_SMEM_FLOATS * 4>>>(qk, v);
    combine_kernel<<<(BB * SS * 16) / 256, 256>>>(out);
}

// round 4
// speedup vs baseline: 1.0271x; 1.0271x over previous
#include <cuda_runtime.h>

#define BB 16
#define SS 4096
#define DD 64
#define NH 8
#define NB 64

typedef unsigned long long ull;

// ---- packed f32x2 helpers (FFMA2: 2 fp32 FMAs per issue slot) ----
#define LDSV2(a,b,addr) asm volatile("ld.shared.v2.u64 {%0,%1},[%2];" : "=l"(a),"=l"(b) : "r"(addr))
#define FMA2(d,a,b,c)   asm("fma.rn.f32x2 %0,%1,%2,%3;" : "=l"(d) : "l"(a),"l"(b),"l"(c))
#define MUL2(d,a,b)     asm("mul.rn.f32x2 %0,%1,%2;"    : "=l"(d) : "l"(a),"l"(b))
#define ADD2(d,a,b)     asm("add.rn.f32x2 %0,%1,%2;"    : "=l"(d) : "l"(a),"l"(b))
#define PK2(d,lo,hi)    asm("mov.b64 %0,{%1,%2};" : "=l"(d) : "f"(lo),"f"(hi))
#define UPK2(lo,hi,d)   asm("mov.b64 {%0,%1},%2;" : "=f"(lo),"=f"(hi) : "l"(d))

__device__ __forceinline__ unsigned smaddr(const void* p) {
    unsigned a;
    asm("{ .reg .u64 t; cvta.to.shared.u64 t, %1; cvt.u32.u64 %0, t; }" : "=r"(a) : "l"(p));
    return a;
}

// ---------------- scratch (static __device__, allocation-free) ----------------
__device__ int   g_buckets[BB * NH * SS];
__device__ int   g_st[BB * NH * SS];
__device__ float g_lse[BB * NH * SS];
__device__ float g_o[(size_t)BB * NH * SS * DD];

// =============================================================================
// K1: LSH hashing (packed f32x2 FMA).
// =============================================================================
__global__ __launch_bounds__(256) void hash_kernel(const float* __restrict__ qk,
                                                   const float* __restrict__ rot)
{
    extern __shared__ float rs[];        // [64 f][256 (h*32+i)] = 64 KB
    int b   = blockIdx.y;
    int tid = threadIdx.x;
    const float* rg = rot + (size_t)b * DD * NH * 32;
    #pragma unroll
    for (int k = 0; k < 64; k++) rs[tid + k * 256] = rg[tid + k * 256];
    __syncthreads();

    int t = blockIdx.x * 256 + tid;
    float q[64];
    const float4* qg = (const float4*)(qk + ((size_t)b * SS + t) * DD);
    #pragma unroll
    for (int c = 0; c < 16; c++) {
        float4 u = qg[c];
        q[4*c] = u.x; q[4*c+1] = u.y; q[4*c+2] = u.z; q[4*c+3] = u.w;
    }

    unsigned rsb = smaddr(rs);

    #pragma unroll 1
    for (int h = 0; h < NH; h++) {
        ull va[16];
        #pragma unroll
        for (int k = 0; k < 16; k++) va[k] = 0ull;
        unsigned hb = rsb + h * 128;
        #pragma unroll 4
        for (int f = 0; f < 64; f++) {
            ull q2; PK2(q2, q[f], q[f]);
            unsigned rb = hb + f * 1024;
            #pragma unroll
            for (int c = 0; c < 8; c++) {
                ull r0, r1; LDSV2(r0, r1, rb + c * 16);
                FMA2(va[2*c],   q2, r0, va[2*c]);
                FMA2(va[2*c+1], q2, r1, va[2*c+1]);
            }
        }
        float vals[32];
        #pragma unroll
        for (int k = 0; k < 16; k++) UPK2(vals[2*k], vals[2*k+1], va[k]);
        // argmax over [vals, -vals], first occurrence wins
        float best = vals[0]; int arg = 0;
        #pragma unroll
        for (int i = 1; i < 32; i++) if (vals[i] > best) { best = vals[i]; arg = i; }
        #pragma unroll
        for (int i = 0; i < 32; i++) { float vv = -vals[i]; if (vv > best) { best = vv; arg = 32 + i; } }
        g_buckets[(b * NH + h) * SS + t] = arg;
    }
}

// =============================================================================
// K2: stable counting sort per (b,h)  (unchanged — 5 us)
// =============================================================================
__global__ __launch_bounds__(128) void sort_kernel()
{
    __shared__ int hist[64 * 130];
    __shared__ int base[64];
    int bh  = blockIdx.x;
    int tid = threadIdx.x;

    for (int k = tid; k < 64 * 130; k += 128) hist[k] = 0;
    __syncthreads();

    const int* bks = g_buckets + bh * SS;
    int myb[32];
    #pragma unroll
    for (int k = 0; k < 32; k++) {
        int bb = bks[tid * 32 + k];
        myb[k] = bb;
        hist[bb * 130 + tid] += 1;
    }
    __syncthreads();

    if (tid < 64) {
        int run = 0;
        for (int j = 0; j < 128; j++) {
            int vv = hist[tid * 130 + j];
            hist[tid * 130 + j] = run;
            run += vv;
        }
        base[tid] = run;
    }
    __syncthreads();
    if (tid == 0) {
        int run = 0;
        for (int u = 0; u < 64; u++) { int vv = base[u]; base[u] = run; run += vv; }
    }
    __syncthreads();

    int* st = g_st + bh * SS;
    #pragma unroll
    for (int k = 0; k < 32; k++) {
        int bb  = myb[k];
        int off = hist[bb * 130 + tid];
        hist[bb * 130 + tid] = off + 1;
        st[base[bb] + off] = tid * 32 + k;
    }
}

// =============================================================================
// K3: chunked attention with packed f32x2 FMA mainloops.
// =============================================================================
#define KNS 68
#define DTS 133
#define SM_KN   0
#define SM_VS   (128 * KNS)
#define SM_DOTS (2 * 128 * KNS)
#define SM_QN   (SM_DOTS + 64 * DTS)
#define SM_RED  (SM_QN + 64)
#define SM_IDS  (SM_RED + 256)
#define ATT_SMEM_FLOATS (SM_IDS + 128)

__global__ __launch_bounds__(256, 2) void attn_kernel(const float* __restrict__ qk,
                                                      const float* __restrict__ vin)
{
    extern __shared__ float sm[];
    float* kn   = sm + SM_KN;
    float* vs   = sm + SM_VS;
    float* dots = sm + SM_DOTS;
    float* qn   = sm + SM_QN;
    float* red  = sm + SM_RED;
    int*   ids  = (int*)(sm + SM_IDS);

    int b   = blockIdx.y;
    int c   = blockIdx.x;
    int tid = threadIdx.x;
    int h   = c >> 6,  lc  = c & 63;
    int pcn = (c + 511) & 511;
    int ph  = pcn >> 6, plc = pcn & 63;

    if (tid < 128) {
        int rr = tid;
        ids[rr] = (rr < 64) ? g_st[(b * NH + h)  * SS + lc  * 64 + rr]
                            : g_st[(b * NH + ph) * SS + plc * 64 + (rr - 64)];
    }
    __syncthreads();

    // ---- gather rows, normalize keys ----
    {
        int r = tid >> 1, part = tid & 1;
        int t = ids[r];
        const float4* srck = (const float4*)(qk  + ((size_t)b * SS + t) * DD) + part * 8;
        const float4* srcv = (const float4*)(vin + ((size_t)b * SS + t) * DD) + part * 8;
        float4* dstk = (float4*)(kn + r * KNS) + part * 8;
        float4* dstv = (float4*)(vs + r * KNS) + part * 8;
        float4 xr[8];
        float  ssq = 0.f;
        #pragma unroll
        for (int c4 = 0; c4 < 8; c4++) {
            float4 x = srck[c4]; xr[c4] = x;
            ssq += x.x * x.x + x.y * x.y + x.z * x.z + x.w * x.w;
            dstv[c4] = srcv[c4];
        }
        ssq += __shfl_xor_sync(0xffffffffu, ssq, 1);
        float norm = sqrtf(ssq);
        float inv  = 1.0f / fmaxf(norm, 1e-12f);
        #pragma unroll
        for (int c4 = 0; c4 < 8; c4++) {
            float4 x = xr[c4];
            x.x *= inv; x.y *= inv; x.z *= inv; x.w *= inv;
            dstk[c4] = x;
        }
        if (part == 0 && r < 64) qn[r] = norm * 0.125f;
    }
    __syncthreads();

    int i  = tid & 63;
    int qq = tid >> 6;
    int ti = ids[i];

    unsigned knb = smaddr(kn);
    unsigned vsb = smaddr(vs);

    // query packed in registers: khat_i * (norm_i * 0.125) as 32 f32x2 pairs
    ull qp[32];
    {
        unsigned qb = knb + i * (KNS * 4);
        #pragma unroll
        for (int c4 = 0; c4 < 16; c4++) LDSV2(qp[2*c4], qp[2*c4+1], qb + c4 * 16);
        float sc = qn[i];
        ull sc2; PK2(sc2, sc, sc);
        #pragma unroll
        for (int k = 0; k < 32; k++) MUL2(qp[k], qp[k], sc2);
    }

    // ---- QK^T (packed): this thread covers j in [qq*32, qq*32+32) ----
    int j0 = qq * 32;
    #pragma unroll 1
    for (int j = j0; j < j0 + 32; j++) {
        unsigned kb = knb + j * (KNS * 4);
        ull aA = 0ull, aB = 0ull, aC = 0ull, aD = 0ull;
        #pragma unroll
        for (int c8 = 0; c8 < 8; c8++) {
            ull k0, k1, k2, k3;
            LDSV2(k0, k1, kb + c8 * 32);
            LDSV2(k2, k3, kb + c8 * 32 + 16);
            FMA2(aA, qp[4*c8],   k0, aA);
            FMA2(aB, qp[4*c8+1], k1, aB);
            FMA2(aC, qp[4*c8+2], k2, aC);
            FMA2(aD, qp[4*c8+3], k3, aD);
        }
        ADD2(aA, aA, aB);
        ADD2(aC, aC, aD);
        ADD2(aA, aA, aC);
        float lo, hi; UPK2(lo, hi, aA);
        float acc = lo + hi;
        if (ti == ids[j]) acc = -50000.0f;
        dots[i * DTS + j] = acc;
    }
    __syncthreads();

    // ---- softmax with lse ----
    float m = -3.4e38f;
    #pragma unroll
    for (int j = 0; j < 32; j++) m = fmaxf(m, dots[i * DTS + j0 + j]);
    red[i * 4 + qq] = m;
    __syncthreads();
    float rm = fmaxf(fmaxf(red[i*4+0], red[i*4+1]), fmaxf(red[i*4+2], red[i*4+3]));
    __syncthreads();
    float sme = 0.f;
    #pragma unroll
    for (int j = 0; j < 32; j++) {
        float p = expf(dots[i * DTS + j0 + j] - rm);
        dots[i * DTS + j0 + j] = p;
        sme += p;
    }
    red[i * 4 + qq] = sme;
    __syncthreads();
    float rsum = (red[i*4+0] + red[i*4+1]) + (red[i*4+2] + red[i*4+3]);
    if (qq == 0) g_lse[(b * NH + h) * SS + ti] = rm + logf(rsum);
    float rinv = 1.0f / rsum;

    // ---- P@V (packed): this thread covers d in [qq*16, qq*16+16) ----
    ull o[8];
    #pragma unroll
    for (int k = 0; k < 8; k++) o[k] = 0ull;
    unsigned vq = vsb + qq * 64;
    #pragma unroll 2
    for (int j = 0; j < 128; j++) {
        float p = dots[i * DTS + j];
        ull p2; PK2(p2, p, p);
        unsigned vb = vq + j * (KNS * 4);
        ull v0, v1, v2, v3, v4, v5, v6, v7;
        LDSV2(v0, v1, vb);
        LDSV2(v2, v3, vb + 16);
        LDSV2(v4, v5, vb + 32);
        LDSV2(v6, v7, vb + 48);
        FMA2(o[0], p2, v0, o[0]);
        FMA2(o[1], p2, v1, o[1]);
        FMA2(o[2], p2, v2, o[2]);
        FMA2(o[3], p2, v3, o[3]);
        FMA2(o[4], p2, v4, o[4]);
        FMA2(o[5], p2, v5, o[5]);
        FMA2(o[6], p2, v6, o[6]);
        FMA2(o[7], p2, v7, o[7]);
    }
    ull r2; PK2(r2, rinv, rinv);
    #pragma unroll
    for (int k = 0; k < 8; k++) MUL2(o[k], o[k], r2);

    ulonglong2* dst = (ulonglong2*)(g_o + (((size_t)(b * NH + h) * SS + ti) * DD) + qq * 16);
    dst[0] = make_ulonglong2(o[0], o[1]);
    dst[1] = make_ulonglong2(o[2], o[3]);
    dst[2] = make_ulonglong2(o[4], o[5]);
    dst[3] = make_ulonglong2(o[6], o[7]);
}

// =============================================================================
// K4: combine hash rounds (already at 75% DRAM — unchanged)
// =============================================================================
__global__ __launch_bounds__(256) void combine_kernel(float* __restrict__ out)
{
    int gid = blockIdx.x * 256 + threadIdx.x;
    int d4  = gid & 15;
    int bt  = gid >> 4;
    int b   = bt >> 12;
    int t   = bt & 4095;

    float l[8]; float m = -3.4e38f;
    #pragma unroll
    for (int h = 0; h < 8; h++) { l[h] = g_lse[(b * NH + h) * SS + t]; m = fmaxf(m, l[h]); }
    float w[8]; float Z = 0.f;
    #pragma unroll
    for (int h = 0; h < 8; h++) { w[h] = expf(l[h] - m); Z += w[h]; }
    float invZ = 1.0f / Z;

    float4 a = {0,0,0,0};
    #pragma unroll
    for (int h = 0; h < 8; h++) {
        float4 ov = *((const float4*)(g_o + ((size_t)(b * NH + h) * SS + t) * DD) + d4);
        a.x = fmaf(w[h], ov.x, a.x);
        a.y = fmaf(w[h], ov.y, a.y);
        a.z = fmaf(w[h], ov.z, a.z);
        a.w = fmaf(w[h], ov.w, a.w);
    }
    a.x *= invZ; a.y *= invZ; a.z *= invZ; a.w *= invZ;
    ((float4*)out)[(size_t)bt * 16 + d4] = a;
}

// =============================================================================
extern "C" void kernel_launch(void* const* d_in, const int* in_sizes, int n_in,
                              void* d_out, int out_size)
{
    const float* qk  = (const float*)d_in[0];
    const float* v   = (const float*)d_in[1];
    const float* rot = (const float*)d_in[2];
    float* out = (float*)d_out;

    cudaFuncSetAttribute(hash_kernel, cudaFuncAttributeMaxDynamicSharedMemorySize, 65536);
    cudaFuncSetAttribute(attn_kernel, cudaFuncAttributeMaxDynamicSharedMemorySize, ATT_SMEM_FLOATS * 4);

    hash_kernel<<<dim3(SS / 256, BB), 256, 65536>>>(qk, rot);
    sort_kernel<<<BB * NH, 128>>>();
    attn_kernel<<<dim3(512, BB), 256, ATT_SMEM_FLOATS * 4>>>(qk, v);
    combine_kernel<<<(BB * SS * 16) / 256, 256>>>(out);
}

// round 7
// speedup vs baseline: 1.3480x; 1.3125x over previous
#include <cuda_runtime.h>

#define BB 16
#define SS 4096
#define DD 64
#define NH 8
#define NB 64

typedef unsigned long long ull;

// ---- packed f32x2 helpers ----
#define LDSV2(a,b,addr) asm volatile("ld.shared.v2.u64 {%0,%1},[%2];" : "=l"(a),"=l"(b) : "r"(addr))
#define FMA2(d,a,b,c)   asm("fma.rn.f32x2 %0,%1,%2,%3;" : "=l"(d) : "l"(a),"l"(b),"l"(c))
#define MUL2(d,a,b)     asm("mul.rn.f32x2 %0,%1,%2;"    : "=l"(d) : "l"(a),"l"(b))
#define ADD2(d,a,b)     asm("add.rn.f32x2 %0,%1,%2;"    : "=l"(d) : "l"(a),"l"(b))
#define PK2(d,lo,hi)    asm("mov.b64 %0,{%1,%2};" : "=l"(d) : "f"(lo),"f"(hi))
#define UPK2(lo,hi,d)   asm("mov.b64 {%0,%1},%2;" : "=f"(lo),"=f"(hi) : "l"(d))

__device__ __forceinline__ unsigned smaddr(const void* p) {
    unsigned a;
    asm("{ .reg .u64 t; cvta.to.shared.u64 t, %1; cvt.u32.u64 %0, t; }" : "=r"(a) : "l"(p));
    return a;
}

// ---------------- scratch ----------------
__device__ int   g_buckets[BB * NH * SS];
__device__ int   g_st[BB * NH * SS];
__device__ float g_lse[BB * NH * SS];
__device__ float g_o[(size_t)BB * NH * SS * DD];

// =============================================================================
// K1: LSH hashing
// =============================================================================
__global__ __launch_bounds__(256) void hash_kernel(const float* __restrict__ qk,
                                                   const float* __restrict__ rot)
{
    extern __shared__ float rs[];
    int b   = blockIdx.y;
    int tid = threadIdx.x;
    const float* rg = rot + (size_t)b * DD * NH * 32;
    #pragma unroll
    for (int k = 0; k < 64; k++) rs[tid + k * 256] = rg[tid + k * 256];
    __syncthreads();

    int t = blockIdx.x * 256 + tid;
    float q[64];
    const float4* qg = (const float4*)(qk + ((size_t)b * SS + t) * DD);
    #pragma unroll
    for (int c = 0; c < 16; c++) {
        float4 u = qg[c];
        q[4*c] = u.x; q[4*c+1] = u.y; q[4*c+2] = u.z; q[4*c+3] = u.w;
    }

    unsigned rsb = smaddr(rs);

    #pragma unroll 1
    for (int h = 0; h < NH; h++) {
        ull va[16];
        #pragma unroll
        for (int k = 0; k < 16; k++) va[k] = 0ull;
        unsigned hb = rsb + h * 128;
        #pragma unroll 4
        for (int f = 0; f < 64; f++) {
            ull q2; PK2(q2, q[f], q[f]);
            unsigned rb = hb + f * 1024;
            #pragma unroll
            for (int c = 0; c < 8; c++) {
                ull r0, r1; LDSV2(r0, r1, rb + c * 16);
                FMA2(va[2*c],   q2, r0, va[2*c]);
                FMA2(va[2*c+1], q2, r1, va[2*c+1]);
            }
        }
        float vals[32];
        #pragma unroll
        for (int k = 0; k < 16; k++) UPK2(vals[2*k], vals[2*k+1], va[k]);
        float best = vals[0]; int arg = 0;
        #pragma unroll
        for (int i = 1; i < 32; i++) if (vals[i] > best) { best = vals[i]; arg = i; }
        #pragma unroll
        for (int i = 0; i < 32; i++) { float vv = -vals[i]; if (vv > best) { best = vv; arg = 32 + i; } }
        g_buckets[(b * NH + h) * SS + t] = arg;
    }
}

// =============================================================================
// K2: stable counting sort per (b,h)
// =============================================================================
__global__ __launch_bounds__(128) void sort_kernel()
{
    __shared__ int hist[64 * 130];
    __shared__ int base[64];
    int bh  = blockIdx.x;
    int tid = threadIdx.x;

    for (int k = tid; k < 64 * 130; k += 128) hist[k] = 0;
    __syncthreads();

    const int* bks = g_buckets + bh * SS;
    int myb[32];
    #pragma unroll
    for (int k = 0; k < 32; k++) {
        int bb = bks[tid * 32 + k];
        myb[k] = bb;
        hist[bb * 130 + tid] += 1;
    }
    __syncthreads();

    if (tid < 64) {
        int run = 0;
        for (int j = 0; j < 128; j++) {
            int vv = hist[tid * 130 + j];
            hist[tid * 130 + j] = run;
            run += vv;
        }
        base[tid] = run;
    }
    __syncthreads();
    if (tid == 0) {
        int run = 0;
        for (int u = 0; u < 64; u++) { int vv = base[u]; base[u] = run; run += vv; }
    }
    __syncthreads();

    int* st = g_st + bh * SS;
    #pragma unroll
    for (int k = 0; k < 32; k++) {
        int bb  = myb[k];
        int off = hist[bb * 130 + tid];
        hist[bb * 130 + tid] = off + 1;
        st[base[bb] + off] = tid * 32 + k;
    }
}

// =============================================================================
// K3: chunked attention, register-tiled micro-GEMMs.
// smem (floats): kT[64][132] (overlaid by dots[64][133]) | vs[128][68] | qn | red | ids
// 70656 bytes -> 3 blocks/SM.
// =============================================================================
#define KTS 132
#define DTS 133
#define VNS 68
#define SM_VS   8512
#define SM_QN   17216
#define SM_RED  17280
#define SM_IDS  17536
#define ATT_SMEM_FLOATS 17664

__global__ __launch_bounds__(256, 3) void attn_kernel(const float* __restrict__ qk,
                                                      const float* __restrict__ vin)
{
    extern __shared__ float sm[];
    float* kT   = sm;                    // also dots after QK
    float* dts  = sm;
    float* vs   = sm + SM_VS;
    float* qn   = sm + SM_QN;
    float* red  = sm + SM_RED;
    int*   ids  = (int*)(sm + SM_IDS);

    int b   = blockIdx.y;
    int c   = blockIdx.x;
    int tid = threadIdx.x;
    int h   = c >> 6,  lc  = c & 63;
    int pcn = (c + 511) & 511;
    int ph  = pcn >> 6, plc = pcn & 63;

    if (tid < 128) {
        int rr = tid;
        ids[rr] = (rr < 64) ? g_st[(b * NH + h)  * SS + lc  * 64 + rr]
                            : g_st[(b * NH + ph) * SS + plc * 64 + (rr - 64)];
    }
    __syncthreads();

    // ---- gather: V row-major, K normalized + transposed into kT[f][j] ----
    {
        int r = tid >> 1, part = tid & 1;
        int t = ids[r];
        const float4* srck = (const float4*)(qk  + ((size_t)b * SS + t) * DD) + part * 8;
        const float4* srcv = (const float4*)(vin + ((size_t)b * SS + t) * DD) + part * 8;
        float4* dstv = (float4*)(vs + r * VNS) + part * 8;
        float4 xr[8];
        float  ssq = 0.f;
        #pragma unroll
        for (int c4 = 0; c4 < 8; c4++) {
            float4 x = srck[c4]; xr[c4] = x;
            ssq += x.x * x.x + x.y * x.y + x.z * x.z + x.w * x.w;
            dstv[c4] = srcv[c4];
        }
        ssq += __shfl_xor_sync(0xffffffffu, ssq, 1);
        float norm = sqrtf(ssq);
        float inv  = 1.0f / fmaxf(norm, 1e-12f);
        int f0 = part * 32;
        #pragma unroll
        for (int c4 = 0; c4 < 8; c4++) {
            float4 x = xr[c4];
            kT[(f0 + 4*c4 + 0) * KTS + r] = x.x * inv;
            kT[(f0 + 4*c4 + 1) * KTS + r] = x.y * inv;
            kT[(f0 + 4*c4 + 2) * KTS + r] = x.z * inv;
            kT[(f0 + 4*c4 + 3) * KTS + r] = x.w * inv;
        }
        if (part == 0 && r < 64) qn[r] = norm * 0.125f;
    }
    __syncthreads();

    // ================= QK^T: 4 queries x 8 keys per thread =================
    int it = tid >> 4;
    int jt = tid & 15;
    int i0 = it * 4;

    unsigned A   = smaddr(sm);
    unsigned VSB = smaddr(vs);

    ull acc[16];
    #pragma unroll
    for (int k = 0; k < 16; k++) acc[k] = 0ull;

    #pragma unroll 4
    for (int f = 0; f < 64; f++) {
        unsigned rb = A + f * (KTS * 4);
        ull q01, q23; LDSV2(q01, q23, rb + i0 * 4);
        ull kA0, kA1; LDSV2(kA0, kA1, rb + jt * 16);
        ull kB0, kB1; LDSV2(kB0, kB1, rb + 256 + jt * 16);   // j+64: 64 floats = 256 B
        float qa, qb, qc, qd;
        UPK2(qa, qb, q01); UPK2(qc, qd, q23);
        ull qA, qB, qC, qD;
        PK2(qA, qa, qa); PK2(qB, qb, qb); PK2(qC, qc, qc); PK2(qD, qd, qd);
        FMA2(acc[ 0], qA, kA0, acc[ 0]); FMA2(acc[ 1], qA, kA1, acc[ 1]);
        FMA2(acc[ 2], qA, kB0, acc[ 2]); FMA2(acc[ 3], qA, kB1, acc[ 3]);
        FMA2(acc[ 4], qB, kA0, acc[ 4]); FMA2(acc[ 5], qB, kA1, acc[ 5]);
        FMA2(acc[ 6], qB, kB0, acc[ 6]); FMA2(acc[ 7], qB, kB1, acc[ 7]);
        FMA2(acc[ 8], qC, kA0, acc[ 8]); FMA2(acc[ 9], qC, kA1, acc[ 9]);
        FMA2(acc[10], qC, kB0, acc[10]); FMA2(acc[11], qC, kB1, acc[11]);
        FMA2(acc[12], qD, kA0, acc[12]); FMA2(acc[13], qD, kA1, acc[13]);
        FMA2(acc[14], qD, kB0, acc[14]); FMA2(acc[15], qD, kB1, acc[15]);
    }

    int   idi[4];  float qs[4];
    int   idjA[4], idjB[4];
    #pragma unroll
    for (int li = 0; li < 4; li++) { idi[li] = ids[i0 + li]; qs[li] = qn[i0 + li]; }
    #pragma unroll
    for (int lj = 0; lj < 4; lj++) { idjA[lj] = ids[4*jt + lj]; idjB[lj] = ids[64 + 4*jt + lj]; }

    __syncthreads();   // all kT reads done; safe to overlay with dots

    #pragma unroll
    for (int li = 0; li < 4; li++) {
        ull s2; PK2(s2, qs[li], qs[li]);
        int rowb = (i0 + li) * DTS;
        #pragma unroll
        for (int jp = 0; jp < 4; jp++) {
            ull a = acc[li * 4 + jp];
            MUL2(a, a, s2);
            float lo, hi; UPK2(lo, hi, a);
            int jlo, jv0;
            if (jp < 2) { jv0 = 4*jt + 2*jp;          jlo = 2*jp; }
            else        { jv0 = 64 + 4*jt + 2*(jp-2); jlo = 2*(jp-2); }
            int e0 = (jp < 2) ? idjA[jlo]   : idjB[jlo];
            int e1 = (jp < 2) ? idjA[jlo+1] : idjB[jlo+1];
            if (idi[li] == e0) lo = -50000.0f;
            if (idi[li] == e1) hi = -50000.0f;
            dts[rowb + jv0]     = lo;
            dts[rowb + jv0 + 1] = hi;
        }
    }
    __syncthreads();

    // ================= softmax + lse =================
    int i  = tid & 63;
    int qq = tid >> 6;
    int j0 = qq * 32;
    int ti = ids[i];

    float m = -3.4e38f;
    #pragma unroll
    for (int j = 0; j < 32; j++) m = fmaxf(m, dts[i * DTS + j0 + j]);
    red[i * 4 + qq] = m;
    __syncthreads();
    float rm = fmaxf(fmaxf(red[i*4+0], red[i*4+1]), fmaxf(red[i*4+2], red[i*4+3]));
    __syncthreads();
    float sme = 0.f;
    #pragma unroll
    for (int j = 0; j < 32; j++) {
        float p = expf(dts[i * DTS + j0 + j] - rm);
        dts[i * DTS + j0 + j] = p;
        sme += p;
    }
    red[i * 4 + qq] = sme;
    __syncthreads();
    if (qq == 0) {
        float rsum = (red[i*4+0] + red[i*4+1]) + (red[i*4+2] + red[i*4+3]);
        g_lse[(b * NH + h) * SS + ti] = rm + logf(rsum);
    }

    // ================= P@V: 4 queries x 4 dims per thread =================
    int dt = tid & 15;
    int d0 = dt * 4;

    float rinv[4];
    #pragma unroll
    for (int li = 0; li < 4; li++) {
        int ii = i0 + li;
        rinv[li] = 1.0f / ((red[ii*4+0] + red[ii*4+1]) + (red[ii*4+2] + red[ii*4+3]));
    }

    ull o[8];
    #pragma unroll
    for (int k = 0; k < 8; k++) o[k] = 0ull;

    #pragma unroll 4
    for (int j = 0; j < 128; j++) {
        float p0 = dts[(i0 + 0) * DTS + j];
        float p1 = dts[(i0 + 1) * DTS + j];
        float p2 = dts[(i0 + 2) * DTS + j];
        float p3 = dts[(i0 + 3) * DTS + j];
        ull P0, P1, P2, P3;
        PK2(P0, p0, p0); PK2(P1, p1, p1); PK2(P2, p2, p2); PK2(P3, p3, p3);
        ull v01, v23; LDSV2(v01, v23, VSB + j * (VNS * 4) + d0 * 4);
        FMA2(o[0], P0, v01, o[0]); FMA2(o[1], P0, v23, o[1]);
        FMA2(o[2], P1, v01, o[2]); FMA2(o[3], P1, v23, o[3]);
        FMA2(o[4], P2, v01, o[4]); FMA2(o[5], P2, v23, o[5]);
        FMA2(o[6], P3, v01, o[6]); FMA2(o[7], P3, v23, o[7]);
    }

    size_t obase = (size_t)(b * NH + h) * SS;
    #pragma unroll
    for (int li = 0; li < 4; li++) {
        ull r2; PK2(r2, rinv[li], rinv[li]);
        ull a0 = o[li*2], a1 = o[li*2+1];
        MUL2(a0, a0, r2); MUL2(a1, a1, r2);
        float4 v4;
        UPK2(v4.x, v4.y, a0);
        UPK2(v4.z, v4.w, a1);
        *(float4*)(g_o + (obase + ids[i0 + li]) * DD + d0) = v4;
    }
}

// =============================================================================
// K4: combine hash rounds (DRAM-bound, unchanged)
// =============================================================================
__global__ __launch_bounds__(256) void combine_kernel(float* __restrict__ out)
{
    int gid = blockIdx.x * 256 + threadIdx.x;
    int d4  = gid & 15;
    int bt  = gid >> 4;
    int b   = bt >> 12;
    int t   = bt & 4095;

    float l[8]; float m = -3.4e38f;
    #pragma unroll
    for (int h = 0; h < 8; h++) { l[h] = g_lse[(b * NH + h) * SS + t]; m = fmaxf(m, l[h]); }
    float w[8]; float Z = 0.f;
    #pragma unroll
    for (int h = 0; h < 8; h++) { w[h] = expf(l[h] - m); Z += w[h]; }
    float invZ = 1.0f / Z;

    float4 a = {0,0,0,0};
    #pragma unroll
    for (int h = 0; h < 8; h++) {
        float4 ov = *((const float4*)(g_o + ((size_t)(b * NH + h) * SS + t) * DD) + d4);
        a.x = fmaf(w[h], ov.x, a.x);
        a.y = fmaf(w[h], ov.y, a.y);
        a.z = fmaf(w[h], ov.z, a.z);
        a.w = fmaf(w[h], ov.w, a.w);
    }
    a.x *= invZ; a.y *= invZ; a.z *= invZ; a.w *= invZ;
    ((float4*)out)[(size_t)bt * 16 + d4] = a;
}

// =============================================================================
extern "C" void kernel_launch(void* const* d_in, const int* in_sizes, int n_in,
                              void* d_out, int out_size)
{
    const float* qk  = (const float*)d_in[0];
    const float* v   = (const float*)d_in[1];
    const float* rot = (const float*)d_in[2];
    float* out = (float*)d_out;

    cudaFuncSetAttribute(hash_kernel, cudaFuncAttributeMaxDynamicSharedMemorySize, 65536);
    cudaFuncSetAttribute(attn_kernel, cudaFuncAttributeMaxDynamicSharedMemorySize, ATT_SMEM_FLOATS * 4);

    hash_kernel<<<dim3(SS / 256, BB), 256, 65536>>>(qk, rot);
    sort_kernel<<<BB * NH, 128>>>();
    attn_kernel<<<dim3(512, BB), 256, ATT_SMEM_FLOATS * 4>>>(qk, v);
    combine_kernel<<<(BB * SS * 16) / 256, 256>>>(out);
}

// round 8
// speedup vs baseline: 1.3593x; 1.0084x over previous
#include <cuda_runtime.h>

#define BB 16
#define SS 4096
#define DD 64
#define NH 8
#define NB 64

typedef unsigned long long ull;

// ---- packed f32x2 helpers ----
#define LDSV2(a,b,addr) asm volatile("ld.shared.v2.u64 {%0,%1},[%2];" : "=l"(a),"=l"(b) : "r"(addr))
#define FMA2(d,a,b,c)   asm("fma.rn.f32x2 %0,%1,%2,%3;" : "=l"(d) : "l"(a),"l"(b),"l"(c))
#define MUL2(d,a,b)     asm("mul.rn.f32x2 %0,%1,%2;"    : "=l"(d) : "l"(a),"l"(b))
#define ADD2(d,a,b)     asm("add.rn.f32x2 %0,%1,%2;"    : "=l"(d) : "l"(a),"l"(b))
#define PK2(d,lo,hi)    asm("mov.b64 %0,{%1,%2};" : "=l"(d) : "f"(lo),"f"(hi))
#define UPK2(lo,hi,d)   asm("mov.b64 {%0,%1},%2;" : "=f"(lo),"=f"(hi) : "l"(d))

__device__ __forceinline__ unsigned smaddr(const void* p) {
    unsigned a;
    asm("{ .reg .u64 t; cvta.to.shared.u64 t, %1; cvt.u32.u64 %0, t; }" : "=r"(a) : "l"(p));
    return a;
}

// ---------------- scratch ----------------
__device__ int   g_buckets[BB * NH * SS];
__device__ int   g_st[BB * NH * SS];
__device__ float g_lse[BB * NH * SS];
__device__ float g_o[(size_t)BB * NH * SS * DD];

// =============================================================================
// K1: LSH hashing (unchanged)
// =============================================================================
__global__ __launch_bounds__(256) void hash_kernel(const float* __restrict__ qk,
                                                   const float* __restrict__ rot)
{
    extern __shared__ float rs[];
    int b   = blockIdx.y;
    int tid = threadIdx.x;
    const float* rg = rot + (size_t)b * DD * NH * 32;
    #pragma unroll
    for (int k = 0; k < 64; k++) rs[tid + k * 256] = rg[tid + k * 256];
    __syncthreads();

    int t = blockIdx.x * 256 + tid;
    float q[64];
    const float4* qg = (const float4*)(qk + ((size_t)b * SS + t) * DD);
    #pragma unroll
    for (int c = 0; c < 16; c++) {
        float4 u = qg[c];
        q[4*c] = u.x; q[4*c+1] = u.y; q[4*c+2] = u.z; q[4*c+3] = u.w;
    }

    unsigned rsb = smaddr(rs);

    #pragma unroll 1
    for (int h = 0; h < NH; h++) {
        ull va[16];
        #pragma unroll
        for (int k = 0; k < 16; k++) va[k] = 0ull;
        unsigned hb = rsb + h * 128;
        #pragma unroll 4
        for (int f = 0; f < 64; f++) {
            ull q2; PK2(q2, q[f], q[f]);
            unsigned rb = hb + f * 1024;
            #pragma unroll
            for (int c = 0; c < 8; c++) {
                ull r0, r1; LDSV2(r0, r1, rb + c * 16);
                FMA2(va[2*c],   q2, r0, va[2*c]);
                FMA2(va[2*c+1], q2, r1, va[2*c+1]);
            }
        }
        float vals[32];
        #pragma unroll
        for (int k = 0; k < 16; k++) UPK2(vals[2*k], vals[2*k+1], va[k]);
        float best = vals[0]; int arg = 0;
        #pragma unroll
        for (int i = 1; i < 32; i++) if (vals[i] > best) { best = vals[i]; arg = i; }
        #pragma unroll
        for (int i = 0; i < 32; i++) { float vv = -vals[i]; if (vv > best) { best = vv; arg = 32 + i; } }
        g_buckets[(b * NH + h) * SS + t] = arg;
    }
}

// =============================================================================
// K2: stable counting sort per (b,h)  (unchanged)
// =============================================================================
__global__ __launch_bounds__(128) void sort_kernel()
{
    __shared__ int hist[64 * 130];
    __shared__ int base[64];
    int bh  = blockIdx.x;
    int tid = threadIdx.x;

    for (int k = tid; k < 64 * 130; k += 128) hist[k] = 0;
    __syncthreads();

    const int* bks = g_buckets + bh * SS;
    int myb[32];
    #pragma unroll
    for (int k = 0; k < 32; k++) {
        int bb = bks[tid * 32 + k];
        myb[k] = bb;
        hist[bb * 130 + tid] += 1;
    }
    __syncthreads();

    if (tid < 64) {
        int run = 0;
        for (int j = 0; j < 128; j++) {
            int vv = hist[tid * 130 + j];
            hist[tid * 130 + j] = run;
            run += vv;
        }
        base[tid] = run;
    }
    __syncthreads();
    if (tid == 0) {
        int run = 0;
        for (int u = 0; u < 64; u++) { int vv = base[u]; base[u] = run; run += vv; }
    }
    __syncthreads();

    int* st = g_st + bh * SS;
    #pragma unroll
    for (int k = 0; k < 32; k++) {
        int bb  = myb[k];
        int off = hist[bb * 130 + tid];
        hist[bb * 130 + tid] = off + 1;
        st[base[bb] + off] = tid * 32 + k;
    }
}

// =============================================================================
// K3: chunked attention.
// smem (floats): kT[64][132] (overlaid by dots[64][132]) | vT[64][132] | qn | red | ids
// 69376 bytes -> 3 blocks/SM.
// =============================================================================
#define KTS 132
#define DTS 132
#define VTS 132
#define SM_VT   8448
#define SM_QN   16896
#define SM_RED  16960
#define SM_IDS  17216
#define ATT_SMEM_FLOATS 17344

__global__ __launch_bounds__(256, 3) void attn_kernel(const float* __restrict__ qk,
                                                      const float* __restrict__ vin)
{
    extern __shared__ float sm[];
    float* kT   = sm;                    // also dots after QK
    float* dts  = sm;
    float* vT   = sm + SM_VT;
    float* qn   = sm + SM_QN;
    float* red  = sm + SM_RED;
    int*   ids  = (int*)(sm + SM_IDS);

    int b   = blockIdx.y;
    int c   = blockIdx.x;
    int tid = threadIdx.x;
    int h   = c >> 6,  lc  = c & 63;
    int pcn = (c + 511) & 511;
    int ph  = pcn >> 6, plc = pcn & 63;

    if (tid < 128) {
        int rr = tid;
        ids[rr] = (rr < 64) ? g_st[(b * NH + h)  * SS + lc  * 64 + rr]
                            : g_st[(b * NH + ph) * SS + plc * 64 + (rr - 64)];
    }
    __syncthreads();

    // ---- gather: K normalized + transposed into kT[f][j]; V transposed into vT[d][j] ----
    {
        int r = tid >> 1, part = tid & 1;
        int t = ids[r];
        const float4* srck = (const float4*)(qk  + ((size_t)b * SS + t) * DD) + part * 8;
        const float4* srcv = (const float4*)(vin + ((size_t)b * SS + t) * DD) + part * 8;
        float4 xr[8];
        float  ssq = 0.f;
        int f0 = part * 32;
        #pragma unroll
        for (int c4 = 0; c4 < 8; c4++) {
            float4 x = srck[c4]; xr[c4] = x;
            ssq += x.x * x.x + x.y * x.y + x.z * x.z + x.w * x.w;
            float4 v = srcv[c4];
            vT[(f0 + 4*c4 + 0) * VTS + r] = v.x;
            vT[(f0 + 4*c4 + 1) * VTS + r] = v.y;
            vT[(f0 + 4*c4 + 2) * VTS + r] = v.z;
            vT[(f0 + 4*c4 + 3) * VTS + r] = v.w;
        }
        ssq += __shfl_xor_sync(0xffffffffu, ssq, 1);
        float norm = sqrtf(ssq);
        float inv  = 1.0f / fmaxf(norm, 1e-12f);
        #pragma unroll
        for (int c4 = 0; c4 < 8; c4++) {
            float4 x = xr[c4];
            kT[(f0 + 4*c4 + 0) * KTS + r] = x.x * inv;
            kT[(f0 + 4*c4 + 1) * KTS + r] = x.y * inv;
            kT[(f0 + 4*c4 + 2) * KTS + r] = x.z * inv;
            kT[(f0 + 4*c4 + 3) * KTS + r] = x.w * inv;
        }
        if (part == 0 && r < 64) qn[r] = norm * 0.125f;
    }
    __syncthreads();

    // ================= QK^T: 4 queries x 8 keys per thread =================
    int it = tid >> 4;
    int jt = tid & 15;
    int i0 = it * 4;

    unsigned A = smaddr(sm);

    ull acc[16];
    #pragma unroll
    for (int k = 0; k < 16; k++) acc[k] = 0ull;

    #pragma unroll 4
    for (int f = 0; f < 64; f++) {
        unsigned rb = A + f * (KTS * 4);
        ull q01, q23; LDSV2(q01, q23, rb + i0 * 4);
        ull kA0, kA1; LDSV2(kA0, kA1, rb + jt * 16);
        ull kB0, kB1; LDSV2(kB0, kB1, rb + 256 + jt * 16);
        float qa, qb, qc, qd;
        UPK2(qa, qb, q01); UPK2(qc, qd, q23);
        ull qA, qB, qC, qD;
        PK2(qA, qa, qa); PK2(qB, qb, qb); PK2(qC, qc, qc); PK2(qD, qd, qd);
        FMA2(acc[ 0], qA, kA0, acc[ 0]); FMA2(acc[ 1], qA, kA1, acc[ 1]);
        FMA2(acc[ 2], qA, kB0, acc[ 2]); FMA2(acc[ 3], qA, kB1, acc[ 3]);
        FMA2(acc[ 4], qB, kA0, acc[ 4]); FMA2(acc[ 5], qB, kA1, acc[ 5]);
        FMA2(acc[ 6], qB, kB0, acc[ 6]); FMA2(acc[ 7], qB, kB1, acc[ 7]);
        FMA2(acc[ 8], qC, kA0, acc[ 8]); FMA2(acc[ 9], qC, kA1, acc[ 9]);
        FMA2(acc[10], qC, kB0, acc[10]); FMA2(acc[11], qC, kB1, acc[11]);
        FMA2(acc[12], qD, kA0, acc[12]); FMA2(acc[13], qD, kA1, acc[13]);
        FMA2(acc[14], qD, kB0, acc[14]); FMA2(acc[15], qD, kB1, acc[15]);
    }

    int   idi[4];  float qs[4];
    int   idjA[4], idjB[4];
    #pragma unroll
    for (int li = 0; li < 4; li++) { idi[li] = ids[i0 + li]; qs[li] = qn[i0 + li]; }
    #pragma unroll
    for (int lj = 0; lj < 4; lj++) { idjA[lj] = ids[4*jt + lj]; idjB[lj] = ids[64 + 4*jt + lj]; }

    __syncthreads();   // kT reads done; overlay with dots

    #pragma unroll
    for (int li = 0; li < 4; li++) {
        ull s2; PK2(s2, qs[li], qs[li]);
        int rowb = (i0 + li) * DTS;
        #pragma unroll
        for (int jp = 0; jp < 4; jp++) {
            ull a = acc[li * 4 + jp];
            MUL2(a, a, s2);
            float lo, hi; UPK2(lo, hi, a);
            int jlo, jv0;
            if (jp < 2) { jv0 = 4*jt + 2*jp;          jlo = 2*jp; }
            else        { jv0 = 64 + 4*jt + 2*(jp-2); jlo = 2*(jp-2); }
            int e0 = (jp < 2) ? idjA[jlo]   : idjB[jlo];
            int e1 = (jp < 2) ? idjA[jlo+1] : idjB[jlo+1];
            if (idi[li] == e0) lo = -50000.0f;
            if (idi[li] == e1) hi = -50000.0f;
            *(float2*)(dts + rowb + jv0) = make_float2(lo, hi);
        }
    }
    __syncthreads();

    // ================= softmax + lse (float4 passes) =================
    int i  = tid & 63;
    int qq = tid >> 6;
    int ti = ids[i];
    float4* drow = (float4*)(dts + i * DTS) + qq * 8;

    float m = -3.4e38f;
    #pragma unroll
    for (int s = 0; s < 8; s++) {
        float4 u = drow[s];
        m = fmaxf(m, fmaxf(fmaxf(u.x, u.y), fmaxf(u.z, u.w)));
    }
    red[i * 4 + qq] = m;
    __syncthreads();
    float rm = fmaxf(fmaxf(red[i*4+0], red[i*4+1]), fmaxf(red[i*4+2], red[i*4+3]));
    __syncthreads();
    float sme = 0.f;
    #pragma unroll
    for (int s = 0; s < 8; s++) {
        float4 u = drow[s];
        u.x = expf(u.x - rm); u.y = expf(u.y - rm);
        u.z = expf(u.z - rm); u.w = expf(u.w - rm);
        drow[s] = u;
        sme += (u.x + u.y) + (u.z + u.w);
    }
    red[i * 4 + qq] = sme;
    __syncthreads();
    if (qq == 0) {
        float rsum = (red[i*4+0] + red[i*4+1]) + (red[i*4+2] + red[i*4+3]);
        g_lse[(b * NH + h) * SS + ti] = rm + logf(rsum);
    }

    // ================= P@V: pack-free, j-parity accumulators =================
    // thread: queries i = iqp + 16*li (li 0..3), dims d = dqp + 16*ld (ld 0..3)
    int iqp = (tid >> 3) & 15;
    int dqp = ((tid >> 7) << 3) | (tid & 7);

    float rinv[4];
    #pragma unroll
    for (int li = 0; li < 4; li++) {
        int ii = iqp + 16 * li;
        rinv[li] = 1.0f / ((red[ii*4+0] + red[ii*4+1]) + (red[ii*4+2] + red[ii*4+3]));
    }

    unsigned pb[4], vb[4];
    #pragma unroll
    for (int li = 0; li < 4; li++) pb[li] = A + ((iqp + 16*li) * DTS) * 4;
    #pragma unroll
    for (int ld = 0; ld < 4; ld++) vb[ld] = A + (SM_VT + (dqp + 16*ld) * VTS) * 4;

    ull o[16];
    #pragma unroll
    for (int k = 0; k < 16; k++) o[k] = 0ull;

    #pragma unroll 2
    for (int j4 = 0; j4 < 32; j4++) {
        ull p01[4], p23[4];
        #pragma unroll
        for (int li = 0; li < 4; li++) LDSV2(p01[li], p23[li], pb[li] + j4 * 16);
        #pragma unroll
        for (int ld = 0; ld < 4; ld++) {
            ull v01, v23;
            LDSV2(v01, v23, vb[ld] + j4 * 16);
            FMA2(o[0*4+ld], p01[0], v01, o[0*4+ld]);
            FMA2(o[1*4+ld], p01[1], v01, o[1*4+ld]);
            FMA2(o[2*4+ld], p01[2], v01, o[2*4+ld]);
            FMA2(o[3*4+ld], p01[3], v01, o[3*4+ld]);
            FMA2(o[0*4+ld], p23[0], v23, o[0*4+ld]);
            FMA2(o[1*4+ld], p23[1], v23, o[1*4+ld]);
            FMA2(o[2*4+ld], p23[2], v23, o[2*4+ld]);
            FMA2(o[3*4+ld], p23[3], v23, o[3*4+ld]);
        }
    }

    size_t obase = (size_t)(b * NH + h) * SS;
    #pragma unroll
    for (int li = 0; li < 4; li++) {
        float* dst = g_o + (obase + ids[iqp + 16*li]) * DD + dqp;
        #pragma unroll
        for (int ld = 0; ld < 4; ld++) {
            float lo, hi; UPK2(lo, hi, o[li*4 + ld]);
            dst[16 * ld] = (lo + hi) * rinv[li];
        }
    }
}

// =============================================================================
// K4: combine hash rounds (DRAM-bound, unchanged)
// =============================================================================
__global__ __launch_bounds__(256) void combine_kernel(float* __restrict__ out)
{
    int gid = blockIdx.x * 256 + threadIdx.x;
    int d4  = gid & 15;
    int bt  = gid >> 4;
    int b   = bt >> 12;
    int t   = bt & 4095;

    float l[8]; float m = -3.4e38f;
    #pragma unroll
    for (int h = 0; h < 8; h++) { l[h] = g_lse[(b * NH + h) * SS + t]; m = fmaxf(m, l[h]); }
    float w[8]; float Z = 0.f;
    #pragma unroll
    for (int h = 0; h < 8; h++) { w[h] = expf(l[h] - m); Z += w[h]; }
    float invZ = 1.0f / Z;

    float4 a = {0,0,0,0};
    #pragma unroll
    for (int h = 0; h < 8; h++) {
        float4 ov = *((const float4*)(g_o + ((size_t)(b * NH + h) * SS + t) * DD) + d4);
        a.x = fmaf(w[h], ov.x, a.x);
        a.y = fmaf(w[h], ov.y, a.y);
        a.z = fmaf(w[h], ov.z, a.z);
        a.w = fmaf(w[h], ov.w, a.w);
    }
    a.x *= invZ; a.y *= invZ; a.z *= invZ; a.w *= invZ;
    ((float4*)out)[(size_t)bt * 16 + d4] = a;
}

// =============================================================================
extern "C" void kernel_launch(void* const* d_in, const int* in_sizes, int n_in,
                              void* d_out, int out_size)
{
    const float* qk  = (const float*)d_in[0];
    const float* v   = (const float*)d_in[1];
    const float* rot = (const float*)d_in[2];
    float* out = (float*)d_out;

    cudaFuncSetAttribute(hash_kernel, cudaFuncAttributeMaxDynamicSharedMemorySize, 65536);
    cudaFuncSetAttribute(attn_kernel, cudaFuncAttributeMaxDynamicSharedMemorySize, ATT_SMEM_FLOATS * 4);

    hash_kernel<<<dim3(SS / 256, BB), 256, 65536>>>(qk, rot);
    sort_kernel<<<BB * NH, 128>>>();
    attn_kernel<<<dim3(512, BB), 256, ATT_SMEM_FLOATS * 4>>>(qk, v);
    combine_kernel<<<(BB * SS * 16) / 256, 256>>>(out);
}

// round 11
// speedup vs baseline: 1.9870x; 1.4618x over previous
#include <cuda_runtime.h>
#include <cuda_fp16.h>

#define BB 16
#define SS 4096
#define DD 64
#define NH 8
#define NB 64

typedef unsigned long long ull;

// ---- packed f32x2 helpers (hash kernel) ----
#define LDSV2(a,b,addr) asm volatile("ld.shared.v2.u64 {%0,%1},[%2];" : "=l"(a),"=l"(b) : "r"(addr))
#define FMA2(d,a,b,c)   asm("fma.rn.f32x2 %0,%1,%2,%3;" : "=l"(d) : "l"(a),"l"(b),"l"(c))
#define PK2(d,lo,hi)    asm("mov.b64 %0,{%1,%2};" : "=l"(d) : "f"(lo),"f"(hi))
#define UPK2(lo,hi,d)   asm("mov.b64 {%0,%1},%2;" : "=f"(lo),"=f"(hi) : "l"(d))

__device__ __forceinline__ unsigned smaddr(const void* p) {
    unsigned a;
    asm("{ .reg .u64 t; cvta.to.shared.u64 t, %1; cvt.u32.u64 %0, t; }" : "=r"(a) : "l"(p));
    return a;
}
__device__ __forceinline__ unsigned lds32(unsigned a) {
    unsigned v; asm volatile("ld.shared.b32 %0,[%1];" : "=r"(v) : "r"(a)); return v;
}
__device__ __forceinline__ void sts32(unsigned a, unsigned v) {
    asm volatile("st.shared.b32 [%0],%1;" :: "r"(a), "r"(v));
}
__device__ __forceinline__ void sts16(unsigned a, unsigned short v) {
    asm volatile("st.shared.b16 [%0],%1;" :: "r"(a), "h"(v));
}
__device__ __forceinline__ void sts64f(unsigned a, float x, float y) {
    asm volatile("st.shared.v2.f32 [%0],{%1,%2};" :: "r"(a), "f"(x), "f"(y));
}
__device__ __forceinline__ float2 lds64f(unsigned a) {
    float2 r; asm volatile("ld.shared.v2.f32 {%0,%1},[%2];" : "=f"(r.x), "=f"(r.y) : "r"(a)); return r;
}
// HMMA m16n8k16 fp16 in, fp32 accum
__device__ __forceinline__ void mma16816(float* c, unsigned a0, unsigned a1, unsigned a2, unsigned a3,
                                         unsigned b0, unsigned b1) {
    asm volatile("mma.sync.aligned.m16n8k16.row.col.f32.f16.f16.f32 "
                 "{%0,%1,%2,%3}, {%4,%5,%6,%7}, {%8,%9}, {%0,%1,%2,%3};"
                 : "+f"(c[0]), "+f"(c[1]), "+f"(c[2]), "+f"(c[3])
                 : "r"(a0), "r"(a1), "r"(a2), "r"(a3), "r"(b0), "r"(b1));
}
__device__ __forceinline__ unsigned h2u(__half2 h) { return *reinterpret_cast<unsigned*>(&h); }

// ---------------- scratch ----------------
__device__ int   g_buckets[BB * NH * SS];
__device__ int   g_st[BB * NH * SS];
__device__ float g_lse[BB * NH * SS];
__device__ float g_o[(size_t)BB * NH * SS * DD];

// =============================================================================
// K1: LSH hashing (fp32 FFMA2 — bucket argmax must match reference exactly)
// =============================================================================
__global__ __launch_bounds__(256) void hash_kernel(const float* __restrict__ qk,
                                                   const float* __restrict__ rot)
{
    extern __shared__ float rs[];
    int b   = blockIdx.y;
    int tid = threadIdx.x;
    const float* rg = rot + (size_t)b * DD * NH * 32;
    #pragma unroll
    for (int k = 0; k < 64; k++) rs[tid + k * 256] = rg[tid + k * 256];
    __syncthreads();

    int t = blockIdx.x * 256 + tid;
    float q[64];
    const float4* qg = (const float4*)(qk + ((size_t)b * SS + t) * DD);
    #pragma unroll
    for (int c = 0; c < 16; c++) {
        float4 u = qg[c];
        q[4*c] = u.x; q[4*c+1] = u.y; q[4*c+2] = u.z; q[4*c+3] = u.w;
    }

    unsigned rsb = smaddr(rs);

    #pragma unroll 1
    for (int h = 0; h < NH; h++) {
        ull va[16];
        #pragma unroll
        for (int k = 0; k < 16; k++) va[k] = 0ull;
        unsigned hb = rsb + h * 128;
        #pragma unroll 4
        for (int f = 0; f < 64; f++) {
            ull q2; PK2(q2, q[f], q[f]);
            unsigned rb = hb + f * 1024;
            #pragma unroll
            for (int c = 0; c < 8; c++) {
                ull r0, r1; LDSV2(r0, r1, rb + c * 16);
                FMA2(va[2*c],   q2, r0, va[2*c]);
                FMA2(va[2*c+1], q2, r1, va[2*c+1]);
            }
        }
        float vals[32];
        #pragma unroll
        for (int k = 0; k < 16; k++) UPK2(vals[2*k], vals[2*k+1], va[k]);
        float best = vals[0]; int arg = 0;
        #pragma unroll
        for (int i = 1; i < 32; i++) if (vals[i] > best) { best = vals[i]; arg = i; }
        #pragma unroll
        for (int i = 0; i < 32; i++) { float vv = -vals[i]; if (vv > best) { best = vv; arg = 32 + i; } }
        g_buckets[(b * NH + h) * SS + t] = arg;
    }
}

// =============================================================================
// K2: stable counting sort per (b,h)  (unchanged)
// =============================================================================
__global__ __launch_bounds__(128) void sort_kernel()
{
    __shared__ int hist[64 * 130];
    __shared__ int base[64];
    int bh  = blockIdx.x;
    int tid = threadIdx.x;

    for (int k = tid; k < 64 * 130; k += 128) hist[k] = 0;
    __syncthreads();

    const int* bks = g_buckets + bh * SS;
    int myb[32];
    #pragma unroll
    for (int k = 0; k < 32; k++) {
        int bb = bks[tid * 32 + k];
        myb[k] = bb;
        hist[bb * 130 + tid] += 1;
    }
    __syncthreads();

    if (tid < 64) {
        int run = 0;
        for (int j = 0; j < 128; j++) {
            int vv = hist[tid * 130 + j];
            hist[tid * 130 + j] = run;
            run += vv;
        }
        base[tid] = run;
    }
    __syncthreads();
    if (tid == 0) {
        int run = 0;
        for (int u = 0; u < 64; u++) { int vv = base[u]; base[u] = run; run += vv; }
    }
    __syncthreads();

    int* st = g_st + bh * SS;
    #pragma unroll
    for (int k = 0; k < 32; k++) {
        int bb  = myb[k];
        int off = hist[bb * 130 + tid];
        hist[bb * 130 + tid] = off + 1;
        st[base[bb] + off] = tid * 32 + k;
    }
}

// =============================================================================
// K3: chunked attention via HMMA m16n8k16 with fp16 hi/lo splits (3 passes).
// smem bytes:
//   Khi [128][72]h @0      (18432)   <- overlaid by pbuf[64][66]f at epilogue
//   Klo [128][72]h @18432  (18432)
//   Vhi [64][136]h @36864  (17408)   (V transposed: [d][j])
//   Vlo [64][136]h @54272  (17408)
//   qn  f[64]      @71680
//   red f[128]     @71936
//   ids i[128]     @72448
// total 72960 B -> 2 blocks/SM at <=128 regs.
// warp w: m-tile mt=w&3 (16 query rows), j-half jh=w>>2 (64 keys)
// =============================================================================
#define SM_KLO_OFF 18432
#define SM_VHI_OFF 36864
#define SM_VLO_OFF 54272
#define SM_QN_OFF  71680
#define SM_RED_OFF 71936
#define SM_IDS_OFF 72448
#define ATT_SMEM_BYTES 72960

__global__ __launch_bounds__(256, 2) void attn_kernel(const float* __restrict__ qk,
                                                      const float* __restrict__ vin)
{
    extern __shared__ char smc[];
    float* qn  = (float*)(smc + SM_QN_OFF);
    float* red = (float*)(smc + SM_RED_OFF);
    int*   ids = (int*)(smc + SM_IDS_OFF);

    unsigned SB   = smaddr(smc);
    unsigned KhiB = SB;
    unsigned KloB = SB + SM_KLO_OFF;
    unsigned VhiB = SB + SM_VHI_OFF;
    unsigned VloB = SB + SM_VLO_OFF;
    unsigned PbB  = SB;                       // pbuf overlays Khi

    int b   = blockIdx.y;
    int c   = blockIdx.x;
    int tid = threadIdx.x;
    int h   = c >> 6,  lc  = c & 63;
    int pcn = (c + 511) & 511;
    int ph  = pcn >> 6, plc = pcn & 63;

    if (tid < 128) {
        int rr = tid;
        ids[rr] = (rr < 64) ? g_st[(b * NH + h)  * SS + lc  * 64 + rr]
                            : g_st[(b * NH + ph) * SS + plc * 64 + (rr - 64)];
    }
    __syncthreads();

    // ---- gather + fp16 hi/lo split ----
    {
        int r = tid >> 1, part = tid & 1;
        int t = ids[r];
        int f0 = part * 32;
        const float4* srck = (const float4*)(qk  + ((size_t)b * SS + t) * DD) + part * 8;
        const float4* srcv = (const float4*)(vin + ((size_t)b * SS + t) * DD) + part * 8;
        float4 xr[8], vr[8];
        float  ssq = 0.f;
        #pragma unroll
        for (int c4 = 0; c4 < 8; c4++) {
            float4 x = srck[c4]; xr[c4] = x;
            ssq += x.x * x.x + x.y * x.y + x.z * x.z + x.w * x.w;
            vr[c4] = srcv[c4];
        }
        ssq += __shfl_xor_sync(0xffffffffu, ssq, 1);
        float norm = sqrtf(ssq);
        float inv  = 1.0f / fmaxf(norm, 1e-12f);
        #pragma unroll
        for (int c4 = 0; c4 < 8; c4++) {
            float k0 = xr[c4].x * inv, k1 = xr[c4].y * inv;
            float k2 = xr[c4].z * inv, k3 = xr[c4].w * inv;
            unsigned off = ((unsigned)(r * 72 + f0 + 4 * c4)) << 1;
            __half2 h01 = __floats2half2_rn(k0, k1);
            __half2 h23 = __floats2half2_rn(k2, k3);
            sts32(KhiB + off,     h2u(h01));
            sts32(KhiB + off + 4, h2u(h23));
            float2 b01 = __half22float2(h01);
            float2 b23 = __half22float2(h23);
            sts32(KloB + off,     h2u(__floats2half2_rn(k0 - b01.x, k1 - b01.y)));
            sts32(KloB + off + 4, h2u(__floats2half2_rn(k2 - b23.x, k3 - b23.y)));
        }
        #pragma unroll
        for (int c4 = 0; c4 < 8; c4++) {
            float vv[4] = {vr[c4].x, vr[c4].y, vr[c4].z, vr[c4].w};
            #pragma unroll
            for (int e = 0; e < 4; e++) {
                int d = f0 + 4 * c4 + e;
                unsigned off = ((unsigned)(d * 136 + r)) << 1;
                __half hv = __float2half_rn(vv[e]);
                sts16(VhiB + off, __half_as_ushort(hv));
                sts16(VloB + off, __half_as_ushort(__float2half_rn(vv[e] - __half2float(hv))));
            }
        }
        if (part == 0 && r < 64) qn[r] = norm * 0.125f;
    }
    __syncthreads();

    int warp = tid >> 5, lane = tid & 31;
    int g = lane >> 2, tig = lane & 3;
    int mt = warp & 3, jh = warp >> 2;
    int r0 = mt * 16 + g, r1 = r0 + 8;

    // ================= QK^T (3-pass split HMMA) =================
    float C[8][4];
    #pragma unroll
    for (int nt = 0; nt < 8; nt++)
        #pragma unroll
        for (int e = 0; e < 4; e++) C[nt][e] = 0.f;

    #pragma unroll
    for (int kk = 0; kk < 4; kk++) {
        unsigned ao = ((unsigned)(r0 * 72 + kk * 16 + 2 * tig)) << 1;
        unsigned a0  = lds32(KhiB + ao),        a2  = lds32(KhiB + ao + 16);
        unsigned a1  = lds32(KhiB + ao + 1152), a3  = lds32(KhiB + ao + 1152 + 16);
        unsigned al0 = lds32(KloB + ao),        al2 = lds32(KloB + ao + 16);
        unsigned al1 = lds32(KloB + ao + 1152), al3 = lds32(KloB + ao + 1152 + 16);
        #pragma unroll
        for (int nt = 0; nt < 8; nt++) {
            int j = jh * 64 + nt * 8 + g;
            unsigned bo = ((unsigned)(j * 72 + kk * 16 + 2 * tig)) << 1;
            unsigned b0  = lds32(KhiB + bo), b1  = lds32(KhiB + bo + 16);
            unsigned bl0 = lds32(KloB + bo), bl1 = lds32(KloB + bo + 16);
            mma16816(C[nt], a0,  a1,  a2,  a3,  b0,  b1);
            mma16816(C[nt], al0, al1, al2, al3, b0,  b1);
            mma16816(C[nt], a0,  a1,  a2,  a3,  bl0, bl1);
        }
    }

    // ---- scale + self-mask ----
    float q0 = qn[r0], q1 = qn[r1];
    int idi0 = ids[r0], idi1 = ids[r1];
    #pragma unroll
    for (int nt = 0; nt < 8; nt++) {
        int jj = jh * 64 + nt * 8 + 2 * tig;
        int e0 = ids[jj], e1 = ids[jj + 1];
        C[nt][0] *= q0; C[nt][1] *= q0;
        C[nt][2] *= q1; C[nt][3] *= q1;
        if (idi0 == e0) C[nt][0] = -50000.0f;
        if (idi0 == e1) C[nt][1] = -50000.0f;
        if (idi1 == e0) C[nt][2] = -50000.0f;
        if (idi1 == e1) C[nt][3] = -50000.0f;
    }

    // ---- softmax over 128 cols (regs + shfl + cross-warp red) ----
    float m0 = -3.4e38f, m1 = -3.4e38f;
    #pragma unroll
    for (int nt = 0; nt < 8; nt++) {
        m0 = fmaxf(m0, fmaxf(C[nt][0], C[nt][1]));
        m1 = fmaxf(m1, fmaxf(C[nt][2], C[nt][3]));
    }
    m0 = fmaxf(m0, __shfl_xor_sync(0xffffffffu, m0, 1));
    m0 = fmaxf(m0, __shfl_xor_sync(0xffffffffu, m0, 2));
    m1 = fmaxf(m1, __shfl_xor_sync(0xffffffffu, m1, 1));
    m1 = fmaxf(m1, __shfl_xor_sync(0xffffffffu, m1, 2));
    if (tig == 0) { red[r0 * 2 + jh] = m0; red[r1 * 2 + jh] = m1; }
    __syncthreads();
    float rm0 = fmaxf(red[r0 * 2], red[r0 * 2 + 1]);
    float rm1 = fmaxf(red[r1 * 2], red[r1 * 2 + 1]);
    __syncthreads();

    float s0 = 0.f, s1 = 0.f;
    #pragma unroll
    for (int nt = 0; nt < 8; nt++) {
        C[nt][0] = expf(C[nt][0] - rm0);
        C[nt][1] = expf(C[nt][1] - rm0);
        C[nt][2] = expf(C[nt][2] - rm1);
        C[nt][3] = expf(C[nt][3] - rm1);
        s0 += C[nt][0] + C[nt][1];
        s1 += C[nt][2] + C[nt][3];
    }
    s0 += __shfl_xor_sync(0xffffffffu, s0, 1);
    s0 += __shfl_xor_sync(0xffffffffu, s0, 2);
    s1 += __shfl_xor_sync(0xffffffffu, s1, 1);
    s1 += __shfl_xor_sync(0xffffffffu, s1, 2);
    if (tig == 0) { red[r0 * 2 + jh] = s0; red[r1 * 2 + jh] = s1; }
    __syncthreads();
    float rs0 = red[r0 * 2] + red[r0 * 2 + 1];
    float rs1 = red[r1 * 2] + red[r1 * 2 + 1];
    if (jh == 0 && tig == 0) {
        g_lse[(b * NH + h) * SS + idi0] = rm0 + logf(rs0);
        g_lse[(b * NH + h) * SS + idi1] = rm1 + logf(rs1);
    }
    float rinv0 = 1.0f / rs0, rinv1 = 1.0f / rs1;

    // ---- P: C fragments -> A fragments (fp16 hi/lo) ----
    unsigned pah[4][4], pal[4][4];
    #pragma unroll
    for (int kk = 0; kk < 4; kk++) {
        int t0 = 2 * kk, t1 = 2 * kk + 1;
        __half2 hh; float2 bk;
        hh = __floats2half2_rn(C[t0][0], C[t0][1]); pah[kk][0] = h2u(hh); bk = __half22float2(hh);
        pal[kk][0] = h2u(__floats2half2_rn(C[t0][0] - bk.x, C[t0][1] - bk.y));
        hh = __floats2half2_rn(C[t0][2], C[t0][3]); pah[kk][1] = h2u(hh); bk = __half22float2(hh);
        pal[kk][1] = h2u(__floats2half2_rn(C[t0][2] - bk.x, C[t0][3] - bk.y));
        hh = __floats2half2_rn(C[t1][0], C[t1][1]); pah[kk][2] = h2u(hh); bk = __half22float2(hh);
        pal[kk][2] = h2u(__floats2half2_rn(C[t1][0] - bk.x, C[t1][1] - bk.y));
        hh = __floats2half2_rn(C[t1][2], C[t1][3]); pah[kk][3] = h2u(hh); bk = __half22float2(hh);
        pal[kk][3] = h2u(__floats2half2_rn(C[t1][2] - bk.x, C[t1][3] - bk.y));
    }

    // ================= P@V (3-pass split HMMA) =================
    float O[8][4];
    #pragma unroll
    for (int nt = 0; nt < 8; nt++)
        #pragma unroll
        for (int e = 0; e < 4; e++) O[nt][e] = 0.f;

    #pragma unroll
    for (int kk = 0; kk < 4; kk++) {
        #pragma unroll
        for (int nt = 0; nt < 8; nt++) {
            int d = nt * 8 + g;
            unsigned bo = ((unsigned)(d * 136 + jh * 64 + kk * 16 + 2 * tig)) << 1;
            unsigned b0  = lds32(VhiB + bo), b1  = lds32(VhiB + bo + 16);
            unsigned bl0 = lds32(VloB + bo), bl1 = lds32(VloB + bo + 16);
            mma16816(O[nt], pah[kk][0], pah[kk][1], pah[kk][2], pah[kk][3], b0,  b1);
            mma16816(O[nt], pal[kk][0], pal[kk][1], pal[kk][2], pal[kk][3], b0,  b1);
            mma16816(O[nt], pah[kk][0], pah[kk][1], pah[kk][2], pah[kk][3], bl0, bl1);
        }
    }

    // ---- combine j-halves via pbuf (overlay on Khi), write g_o ----
    __syncthreads();   // all K reads long done; pbuf overlay safe
    if (jh == 1) {
        #pragma unroll
        for (int nt = 0; nt < 8; nt++) {
            unsigned o0 = PbB + ((unsigned)(r0 * 66 + nt * 8 + 2 * tig) << 2);
            unsigned o1 = PbB + ((unsigned)(r1 * 66 + nt * 8 + 2 * tig) << 2);
            sts64f(o0, O[nt][0], O[nt][1]);
            sts64f(o1, O[nt][2], O[nt][3]);
        }
    }
    __syncthreads();
    if (jh == 0) {
        size_t ob0 = ((size_t)(b * NH + h) * SS + idi0) * DD;
        size_t ob1 = ((size_t)(b * NH + h) * SS + idi1) * DD;
        #pragma unroll
        for (int nt = 0; nt < 8; nt++) {
            int d = nt * 8 + 2 * tig;
            float2 u0 = lds64f(PbB + ((unsigned)(r0 * 66 + d) << 2));
            float2 u1 = lds64f(PbB + ((unsigned)(r1 * 66 + d) << 2));
            float2 w0 = make_float2((O[nt][0] + u0.x) * rinv0, (O[nt][1] + u0.y) * rinv0);
            float2 w1 = make_float2((O[nt][2] + u1.x) * rinv1, (O[nt][3] + u1.y) * rinv1);
            *(float2*)(g_o + ob0 + d) = w0;
            *(float2*)(g_o + ob1 + d) = w1;
        }
    }
}

// =============================================================================
// K4: combine hash rounds (DRAM-bound, unchanged)
// =============================================================================
__global__ __launch_bounds__(256) void combine_kernel(float* __restrict__ out)
{
    int gid = blockIdx.x * 256 + threadIdx.x;
    int d4  = gid & 15;
    int bt  = gid >> 4;
    int b   = bt >> 12;
    int t   = bt & 4095;

    float l[8]; float m = -3.4e38f;
    #pragma unroll
    for (int h = 0; h < 8; h++) { l[h] = g_lse[(b * NH + h) * SS + t]; m = fmaxf(m, l[h]); }
    float w[8]; float Z = 0.f;
    #pragma unroll
    for (int h = 0; h < 8; h++) { w[h] = expf(l[h] - m); Z += w[h]; }
    float invZ = 1.0f / Z;

    float4 a = {0,0,0,0};
    #pragma unroll
    for (int h = 0; h < 8; h++) {
        float4 ov = *((const float4*)(g_o + ((size_t)(b * NH + h) * SS + t) * DD) + d4);
        a.x = fmaf(w[h], ov.x, a.x);
        a.y = fmaf(w[h], ov.y, a.y);
        a.z = fmaf(w[h], ov.z, a.z);
        a.w = fmaf(w[h], ov.w, a.w);
    }
    a.x *= invZ; a.y *= invZ; a.z *= invZ; a.w *= invZ;
    ((float4*)out)[(size_t)bt * 16 + d4] = a;
}

// =============================================================================
extern "C" void kernel_launch(void* const* d_in, const int* in_sizes, int n_in,
                              void* d_out, int out_size)
{
    const float* qk  = (const float*)d_in[0];
    const float* v   = (const float*)d_in[1];
    const float* rot = (const float*)d_in[2];
    float* out = (float*)d_out;

    cudaFuncSetAttribute(hash_kernel, cudaFuncAttributeMaxDynamicSharedMemorySize, 65536);
    cudaFuncSetAttribute(attn_kernel, cudaFuncAttributeMaxDynamicSharedMemorySize, ATT_SMEM_BYTES);

    hash_kernel<<<dim3(SS / 256, BB), 256, 65536>>>(qk, rot);
    sort_kernel<<<BB * NH, 128>>>();
    attn_kernel<<<dim3(512, BB), 256, ATT_SMEM_BYTES>>>(qk, v);
    combine_kernel<<<(BB * SS * 16) / 256, 256>>>(out);
}

// round 12
// speedup vs baseline: 2.1246x; 1.0693x over previous
#include <cuda_runtime.h>
#include <cuda_fp16.h>

#define BB 16
#define SS 4096
#define DD 64
#define NH 8
#define NB 64

typedef unsigned long long ull;

// ---- packed f32x2 helpers (hash kernel) ----
#define LDSV2(a,b,addr) asm volatile("ld.shared.v2.u64 {%0,%1},[%2];" : "=l"(a),"=l"(b) : "r"(addr))
#define FMA2(d,a,b,c)   asm("fma.rn.f32x2 %0,%1,%2,%3;" : "=l"(d) : "l"(a),"l"(b),"l"(c))
#define PK2(d,lo,hi)    asm("mov.b64 %0,{%1,%2};" : "=l"(d) : "f"(lo),"f"(hi))
#define UPK2(lo,hi,d)   asm("mov.b64 {%0,%1},%2;" : "=f"(lo),"=f"(hi) : "l"(d))

__device__ __forceinline__ unsigned smaddr(const void* p) {
    unsigned a;
    asm("{ .reg .u64 t; cvta.to.shared.u64 t, %1; cvt.u32.u64 %0, t; }" : "=r"(a) : "l"(p));
    return a;
}
__device__ __forceinline__ void sts32(unsigned a, unsigned v) {
    asm volatile("st.shared.b32 [%0],%1;" :: "r"(a), "r"(v));
}
__device__ __forceinline__ void sts64f(unsigned a, float x, float y) {
    asm volatile("st.shared.v2.f32 [%0],{%1,%2};" :: "r"(a), "f"(x), "f"(y));
}
__device__ __forceinline__ float2 lds64f(unsigned a) {
    float2 r; asm volatile("ld.shared.v2.f32 {%0,%1},[%2];" : "=f"(r.x), "=f"(r.y) : "r"(a)); return r;
}
__device__ __forceinline__ void ldsm_x4(unsigned& d0, unsigned& d1, unsigned& d2, unsigned& d3, unsigned a) {
    asm volatile("ldmatrix.sync.aligned.m8n8.x4.shared.b16 {%0,%1,%2,%3}, [%4];"
                 : "=r"(d0), "=r"(d1), "=r"(d2), "=r"(d3) : "r"(a));
}
__device__ __forceinline__ void ldsm_x4t(unsigned& d0, unsigned& d1, unsigned& d2, unsigned& d3, unsigned a) {
    asm volatile("ldmatrix.sync.aligned.m8n8.x4.trans.shared.b16 {%0,%1,%2,%3}, [%4];"
                 : "=r"(d0), "=r"(d1), "=r"(d2), "=r"(d3) : "r"(a));
}
__device__ __forceinline__ void mma16816(float* c, unsigned a0, unsigned a1, unsigned a2, unsigned a3,
                                         unsigned b0, unsigned b1) {
    asm volatile("mma.sync.aligned.m16n8k16.row.col.f32.f16.f16.f32 "
                 "{%0,%1,%2,%3}, {%4,%5,%6,%7}, {%8,%9}, {%0,%1,%2,%3};"
                 : "+f"(c[0]), "+f"(c[1]), "+f"(c[2]), "+f"(c[3])
                 : "r"(a0), "r"(a1), "r"(a2), "r"(a3), "r"(b0), "r"(b1));
}
__device__ __forceinline__ unsigned h2u(__half2 h) { return *reinterpret_cast<unsigned*>(&h); }

// ---------------- scratch ----------------
__device__ int   g_buckets[BB * NH * SS];
__device__ int   g_st[BB * NH * SS];
__device__ float g_lse[BB * NH * SS];
__device__ float g_o[(size_t)BB * NH * SS * DD];

// =============================================================================
// K1: LSH hashing (fp32 — bucket argmax must track reference)
// =============================================================================
__global__ __launch_bounds__(256) void hash_kernel(const float* __restrict__ qk,
                                                   const float* __restrict__ rot)
{
    extern __shared__ float rs[];
    int b   = blockIdx.y;
    int tid = threadIdx.x;
    const float* rg = rot + (size_t)b * DD * NH * 32;
    #pragma unroll
    for (int k = 0; k < 64; k++) rs[tid + k * 256] = rg[tid + k * 256];
    __syncthreads();

    int t = blockIdx.x * 256 + tid;
    float q[64];
    const float4* qg = (const float4*)(qk + ((size_t)b * SS + t) * DD);
    #pragma unroll
    for (int c = 0; c < 16; c++) {
        float4 u = qg[c];
        q[4*c] = u.x; q[4*c+1] = u.y; q[4*c+2] = u.z; q[4*c+3] = u.w;
    }

    unsigned rsb = smaddr(rs);

    #pragma unroll 1
    for (int h = 0; h < NH; h++) {
        ull va[16];
        #pragma unroll
        for (int k = 0; k < 16; k++) va[k] = 0ull;
        unsigned hb = rsb + h * 128;
        #pragma unroll 4
        for (int f = 0; f < 64; f++) {
            ull q2; PK2(q2, q[f], q[f]);
            unsigned rb = hb + f * 1024;
            #pragma unroll
            for (int c = 0; c < 8; c++) {
                ull r0, r1; LDSV2(r0, r1, rb + c * 16);
                FMA2(va[2*c],   q2, r0, va[2*c]);
                FMA2(va[2*c+1], q2, r1, va[2*c+1]);
            }
        }
        float vals[32];
        #pragma unroll
        for (int k = 0; k < 16; k++) UPK2(vals[2*k], vals[2*k+1], va[k]);
        float best = vals[0]; int arg = 0;
        #pragma unroll
        for (int i = 1; i < 32; i++) if (vals[i] > best) { best = vals[i]; arg = i; }
        #pragma unroll
        for (int i = 0; i < 32; i++) { float vv = -vals[i]; if (vv > best) { best = vv; arg = 32 + i; } }
        g_buckets[(b * NH + h) * SS + t] = arg;
    }
}

// =============================================================================
// K2: stable counting sort per (b,h)
// =============================================================================
__global__ __launch_bounds__(128) void sort_kernel()
{
    __shared__ int hist[64 * 130];
    __shared__ int base[64];
    int bh  = blockIdx.x;
    int tid = threadIdx.x;

    for (int k = tid; k < 64 * 130; k += 128) hist[k] = 0;
    __syncthreads();

    const int* bks = g_buckets + bh * SS;
    int myb[32];
    #pragma unroll
    for (int k = 0; k < 32; k++) {
        int bb = bks[tid * 32 + k];
        myb[k] = bb;
        hist[bb * 130 + tid] += 1;
    }
    __syncthreads();

    if (tid < 64) {
        int run = 0;
        for (int j = 0; j < 128; j++) {
            int vv = hist[tid * 130 + j];
            hist[tid * 130 + j] = run;
            run += vv;
        }
        base[tid] = run;
    }
    __syncthreads();
    if (tid == 0) {
        int run = 0;
        for (int u = 0; u < 64; u++) { int vv = base[u]; base[u] = run; run += vv; }
    }
    __syncthreads();

    int* st = g_st + bh * SS;
    #pragma unroll
    for (int k = 0; k < 32; k++) {
        int bb  = myb[k];
        int off = hist[bb * 130 + tid];
        hist[bb * 130 + tid] = off + 1;
        st[base[bb] + off] = tid * 32 + k;
    }
}

// =============================================================================
// K3: HMMA attention with ldmatrix fragment loads.
// smem bytes (stride 72 halves = 144 B everywhere):
//   Khi [128][72]h @0      (18432)  <- pbuf[64][66]f overlay at epilogue
//   Klo [128][72]h @18432
//   Vhi [128][72]h @36864  (row-major [j][d])
//   Vlo [128][72]h @55296
//   qn  f[64]  @73728 | red f[128] @73984 | ids i[128] @74496
// total 75008 B -> 2 blocks/SM.
// =============================================================================
#define SM_KLO_OFF 18432
#define SM_VHI_OFF 36864
#define SM_VLO_OFF 55296
#define SM_QN_OFF  73728
#define SM_RED_OFF 73984
#define SM_IDS_OFF 74496
#define ATT_SMEM_BYTES 75008

__global__ __launch_bounds__(256, 2) void attn_kernel(const float* __restrict__ qk,
                                                      const float* __restrict__ vin)
{
    extern __shared__ char smc[];
    float* qn  = (float*)(smc + SM_QN_OFF);
    float* red = (float*)(smc + SM_RED_OFF);
    int*   ids = (int*)(smc + SM_IDS_OFF);

    unsigned SB   = smaddr(smc);
    unsigned KhiB = SB;
    unsigned KloB = SB + SM_KLO_OFF;
    unsigned VhiB = SB + SM_VHI_OFF;
    unsigned VloB = SB + SM_VLO_OFF;
    unsigned PbB  = SB;

    int b   = blockIdx.y;
    int c   = blockIdx.x;
    int tid = threadIdx.x;
    int h   = c >> 6,  lc  = c & 63;
    int pcn = (c + 511) & 511;
    int ph  = pcn >> 6, plc = pcn & 63;

    if (tid < 128) {
        int rr = tid;
        ids[rr] = (rr < 64) ? g_st[(b * NH + h)  * SS + lc  * 64 + rr]
                            : g_st[(b * NH + ph) * SS + plc * 64 + (rr - 64)];
    }
    __syncthreads();

    // ---- gather + fp16 hi/lo split; K row-major [j][f], V row-major [j][d] ----
    {
        int r = tid >> 1, part = tid & 1;
        int t = ids[r];
        int f0 = part * 32;
        const float4* srck = (const float4*)(qk  + ((size_t)b * SS + t) * DD) + part * 8;
        const float4* srcv = (const float4*)(vin + ((size_t)b * SS + t) * DD) + part * 8;
        float4 xr[8], vr[8];
        float  ssq = 0.f;
        #pragma unroll
        for (int c4 = 0; c4 < 8; c4++) {
            float4 x = srck[c4]; xr[c4] = x;
            ssq += x.x * x.x + x.y * x.y + x.z * x.z + x.w * x.w;
            vr[c4] = srcv[c4];
        }
        ssq += __shfl_xor_sync(0xffffffffu, ssq, 1);
        float norm = sqrtf(ssq);
        float inv  = 1.0f / fmaxf(norm, 1e-12f);
        #pragma unroll
        for (int c4 = 0; c4 < 8; c4++) {
            float k0 = xr[c4].x * inv, k1 = xr[c4].y * inv;
            float k2 = xr[c4].z * inv, k3 = xr[c4].w * inv;
            unsigned off = ((unsigned)(r * 72 + f0 + 4 * c4)) << 1;
            __half2 h01 = __floats2half2_rn(k0, k1);
            __half2 h23 = __floats2half2_rn(k2, k3);
            sts32(KhiB + off,     h2u(h01));
            sts32(KhiB + off + 4, h2u(h23));
            float2 b01 = __half22float2(h01);
            float2 b23 = __half22float2(h23);
            sts32(KloB + off,     h2u(__floats2half2_rn(k0 - b01.x, k1 - b01.y)));
            sts32(KloB + off + 4, h2u(__floats2half2_rn(k2 - b23.x, k3 - b23.y)));
            // V row-major
            float v0 = vr[c4].x, v1 = vr[c4].y, v2 = vr[c4].z, v3 = vr[c4].w;
            __half2 vh01 = __floats2half2_rn(v0, v1);
            __half2 vh23 = __floats2half2_rn(v2, v3);
            sts32(VhiB + off,     h2u(vh01));
            sts32(VhiB + off + 4, h2u(vh23));
            float2 c01 = __half22float2(vh01);
            float2 c23 = __half22float2(vh23);
            sts32(VloB + off,     h2u(__floats2half2_rn(v0 - c01.x, v1 - c01.y)));
            sts32(VloB + off + 4, h2u(__floats2half2_rn(v2 - c23.x, v3 - c23.y)));
        }
        if (part == 0 && r < 64) qn[r] = norm * 0.125f;
    }
    __syncthreads();

    int warp = tid >> 5, lane = tid & 31;
    int g = lane >> 2, tig = lane & 3;
    int mt = warp & 3, jh = warp >> 2;
    int r0 = mt * 16 + g, r1 = r0 + 8;

    // ldmatrix lane-address components
    int lq  = lane >> 3;           // 0..3 (matrix select)
    int lr  = lane & 7;            // row within matrix
    int qk8 = (lq & 1) * 8;        // +8 rows
    int qf16 = (lq >> 1) * 16;     // +8 cols in bytes

    unsigned aAdr = (unsigned)((mt * 16 + qk8 + lr) * 144 + qf16);
    unsigned bAdr[4];
    #pragma unroll
    for (int np = 0; np < 4; np++)
        bAdr[np] = (unsigned)((jh * 64 + np * 16 + qk8 + lr) * 144 + qf16);

    // ================= QK^T (3-pass split HMMA) =================
    float C[8][4];
    #pragma unroll
    for (int nt = 0; nt < 8; nt++)
        #pragma unroll
        for (int e = 0; e < 4; e++) C[nt][e] = 0.f;

    #pragma unroll
    for (int kk = 0; kk < 4; kk++) {
        unsigned ah0, ah1, ah2, ah3, al0, al1, al2, al3;
        ldsm_x4(ah0, ah1, ah2, ah3, KhiB + aAdr + kk * 32);
        ldsm_x4(al0, al1, al2, al3, KloB + aAdr + kk * 32);
        #pragma unroll
        for (int np = 0; np < 4; np++) {
            unsigned bh0, bh1, bh2, bh3, bl0, bl1, bl2, bl3;
            ldsm_x4(bh0, bh1, bh2, bh3, KhiB + bAdr[np] + kk * 32);
            ldsm_x4(bl0, bl1, bl2, bl3, KloB + bAdr[np] + kk * 32);
            mma16816(C[2*np],   ah0, ah1, ah2, ah3, bh0, bh2);
            mma16816(C[2*np],   al0, al1, al2, al3, bh0, bh2);
            mma16816(C[2*np],   ah0, ah1, ah2, ah3, bl0, bl2);
            mma16816(C[2*np+1], ah0, ah1, ah2, ah3, bh1, bh3);
            mma16816(C[2*np+1], al0, al1, al2, al3, bh1, bh3);
            mma16816(C[2*np+1], ah0, ah1, ah2, ah3, bl1, bl3);
        }
    }

    // ---- scale + self-mask ----
    float q0 = qn[r0], q1 = qn[r1];
    int idi0 = ids[r0], idi1 = ids[r1];
    #pragma unroll
    for (int nt = 0; nt < 8; nt++) {
        int jj = jh * 64 + nt * 8 + 2 * tig;
        int e0 = ids[jj], e1 = ids[jj + 1];
        C[nt][0] *= q0; C[nt][1] *= q0;
        C[nt][2] *= q1; C[nt][3] *= q1;
        if (idi0 == e0) C[nt][0] = -50000.0f;
        if (idi0 == e1) C[nt][1] = -50000.0f;
        if (idi1 == e0) C[nt][2] = -50000.0f;
        if (idi1 == e1) C[nt][3] = -50000.0f;
    }

    // ---- softmax (regs + shfl + cross-warp red) ----
    float m0 = -3.4e38f, m1 = -3.4e38f;
    #pragma unroll
    for (int nt = 0; nt < 8; nt++) {
        m0 = fmaxf(m0, fmaxf(C[nt][0], C[nt][1]));
        m1 = fmaxf(m1, fmaxf(C[nt][2], C[nt][3]));
    }
    m0 = fmaxf(m0, __shfl_xor_sync(0xffffffffu, m0, 1));
    m0 = fmaxf(m0, __shfl_xor_sync(0xffffffffu, m0, 2));
    m1 = fmaxf(m1, __shfl_xor_sync(0xffffffffu, m1, 1));
    m1 = fmaxf(m1, __shfl_xor_sync(0xffffffffu, m1, 2));
    if (tig == 0) { red[r0 * 2 + jh] = m0; red[r1 * 2 + jh] = m1; }
    __syncthreads();
    float rm0 = fmaxf(red[r0 * 2], red[r0 * 2 + 1]);
    float rm1 = fmaxf(red[r1 * 2], red[r1 * 2 + 1]);
    __syncthreads();

    float s0 = 0.f, s1 = 0.f;
    #pragma unroll
    for (int nt = 0; nt < 8; nt++) {
        C[nt][0] = __expf(C[nt][0] - rm0);
        C[nt][1] = __expf(C[nt][1] - rm0);
        C[nt][2] = __expf(C[nt][2] - rm1);
        C[nt][3] = __expf(C[nt][3] - rm1);
        s0 += C[nt][0] + C[nt][1];
        s1 += C[nt][2] + C[nt][3];
    }
    s0 += __shfl_xor_sync(0xffffffffu, s0, 1);
    s0 += __shfl_xor_sync(0xffffffffu, s0, 2);
    s1 += __shfl_xor_sync(0xffffffffu, s1, 1);
    s1 += __shfl_xor_sync(0xffffffffu, s1, 2);
    if (tig == 0) { red[r0 * 2 + jh] = s0; red[r1 * 2 + jh] = s1; }
    __syncthreads();
    float rs0 = red[r0 * 2] + red[r0 * 2 + 1];
    float rs1 = red[r1 * 2] + red[r1 * 2 + 1];
    if (jh == 0 && tig == 0) {
        g_lse[(b * NH + h) * SS + idi0] = rm0 + __logf(rs0);
        g_lse[(b * NH + h) * SS + idi1] = rm1 + __logf(rs1);
    }
    float rinv0 = 1.0f / rs0, rinv1 = 1.0f / rs1;

    // ---- P: C fragments -> A fragments (fp16 hi/lo) ----
    unsigned pah[4][4], pal[4][4];
    #pragma unroll
    for (int kk = 0; kk < 4; kk++) {
        int t0 = 2 * kk, t1 = 2 * kk + 1;
        __half2 hh; float2 bk;
        hh = __floats2half2_rn(C[t0][0], C[t0][1]); pah[kk][0] = h2u(hh); bk = __half22float2(hh);
        pal[kk][0] = h2u(__floats2half2_rn(C[t0][0] - bk.x, C[t0][1] - bk.y));
        hh = __floats2half2_rn(C[t0][2], C[t0][3]); pah[kk][1] = h2u(hh); bk = __half22float2(hh);
        pal[kk][1] = h2u(__floats2half2_rn(C[t0][2] - bk.x, C[t0][3] - bk.y));
        hh = __floats2half2_rn(C[t1][0], C[t1][1]); pah[kk][2] = h2u(hh); bk = __half22float2(hh);
        pal[kk][2] = h2u(__floats2half2_rn(C[t1][0] - bk.x, C[t1][1] - bk.y));
        hh = __floats2half2_rn(C[t1][2], C[t1][3]); pah[kk][3] = h2u(hh); bk = __half22float2(hh);
        pal[kk][3] = h2u(__floats2half2_rn(C[t1][2] - bk.x, C[t1][3] - bk.y));
    }

    // ================= P@V (3-pass split HMMA, ldmatrix.trans B) =================
    float O[8][4];
    #pragma unroll
    for (int nt = 0; nt < 8; nt++)
        #pragma unroll
        for (int e = 0; e < 4; e++) O[nt][e] = 0.f;

    #pragma unroll
    for (int kk = 0; kk < 4; kk++) {
        unsigned vRow = (unsigned)((jh * 64 + kk * 16 + qk8 + lr) * 144 + qf16);
        #pragma unroll
        for (int dp = 0; dp < 4; dp++) {
            unsigned vh0, vh1, vh2, vh3, vl0, vl1, vl2, vl3;
            ldsm_x4t(vh0, vh1, vh2, vh3, VhiB + vRow + dp * 32);
            ldsm_x4t(vl0, vl1, vl2, vl3, VloB + vRow + dp * 32);
            mma16816(O[2*dp],   pah[kk][0], pah[kk][1], pah[kk][2], pah[kk][3], vh0, vh1);
            mma16816(O[2*dp],   pal[kk][0], pal[kk][1], pal[kk][2], pal[kk][3], vh0, vh1);
            mma16816(O[2*dp],   pah[kk][0], pah[kk][1], pah[kk][2], pah[kk][3], vl0, vl1);
            mma16816(O[2*dp+1], pah[kk][0], pah[kk][1], pah[kk][2], pah[kk][3], vh2, vh3);
            mma16816(O[2*dp+1], pal[kk][0], pal[kk][1], pal[kk][2], pal[kk][3], vh2, vh3);
            mma16816(O[2*dp+1], pah[kk][0], pah[kk][1], pah[kk][2], pah[kk][3], vl2, vl3);
        }
    }

    // ---- combine j-halves via pbuf (overlay on Khi), write g_o ----
    __syncthreads();
    if (jh == 1) {
        #pragma unroll
        for (int nt = 0; nt < 8; nt++) {
            unsigned o0 = PbB + ((unsigned)(r0 * 66 + nt * 8 + 2 * tig) << 2);
            unsigned o1 = PbB + ((unsigned)(r1 * 66 + nt * 8 + 2 * tig) << 2);
            sts64f(o0, O[nt][0], O[nt][1]);
            sts64f(o1, O[nt][2], O[nt][3]);
        }
    }
    __syncthreads();
    if (jh == 0) {
        size_t ob0 = ((size_t)(b * NH + h) * SS + idi0) * DD;
        size_t ob1 = ((size_t)(b * NH + h) * SS + idi1) * DD;
        #pragma unroll
        for (int nt = 0; nt < 8; nt++) {
            int d = nt * 8 + 2 * tig;
            float2 u0 = lds64f(PbB + ((unsigned)(r0 * 66 + d) << 2));
            float2 u1 = lds64f(PbB + ((unsigned)(r1 * 66 + d) << 2));
            float2 w0 = make_float2((O[nt][0] + u0.x) * rinv0, (O[nt][1] + u0.y) * rinv0);
            float2 w1 = make_float2((O[nt][2] + u1.x) * rinv1, (O[nt][3] + u1.y) * rinv1);
            *(float2*)(g_o + ob0 + d) = w0;
            *(float2*)(g_o + ob1 + d) = w1;
        }
    }
}

// =============================================================================
// K4: combine hash rounds (DRAM-bound, unchanged)
// =============================================================================
__global__ __launch_bounds__(256) void combine_kernel(float* __restrict__ out)
{
    int gid = blockIdx.x * 256 + threadIdx.x;
    int d4  = gid & 15;
    int bt  = gid >> 4;
    int b   = bt >> 12;
    int t   = bt & 4095;

    float l[8]; float m = -3.4e38f;
    #pragma unroll
    for (int h = 0; h < 8; h++) { l[h] = g_lse[(b * NH + h) * SS + t]; m = fmaxf(m, l[h]); }
    float w[8]; float Z = 0.f;
    #pragma unroll
    for (int h = 0; h < 8; h++) { w[h] = __expf(l[h] - m); Z += w[h]; }
    float invZ = 1.0f / Z;

    float4 a = {0,0,0,0};
    #pragma unroll
    for (int h = 0; h < 8; h++) {
        float4 ov = *((const float4*)(g_o + ((size_t)(b * NH + h) * SS + t) * DD) + d4);
        a.x = fmaf(w[h], ov.x, a.x);
        a.y = fmaf(w[h], ov.y, a.y);
        a.z = fmaf(w[h], ov.z, a.z);
        a.w = fmaf(w[h], ov.w, a.w);
    }
    a.x *= invZ; a.y *= invZ; a.z *= invZ; a.w *= invZ;
    ((float4*)out)[(size_t)bt * 16 + d4] = a;
}

// =============================================================================
extern "C" void kernel_launch(void* const* d_in, const int* in_sizes, int n_in,
                              void* d_out, int out_size)
{
    const float* qk  = (const float*)d_in[0];
    const float* v   = (const float*)d_in[1];
    const float* rot = (const float*)d_in[2];
    float* out = (float*)d_out;

    cudaFuncSetAttribute(hash_kernel, cudaFuncAttributeMaxDynamicSharedMemorySize, 65536);
    cudaFuncSetAttribute(attn_kernel, cudaFuncAttributeMaxDynamicSharedMemorySize, ATT_SMEM_BYTES);

    hash_kernel<<<dim3(SS / 256, BB), 256, 65536>>>(qk, rot);
    sort_kernel<<<BB * NH, 128>>>();
    attn_kernel<<<dim3(512, BB), 256, ATT_SMEM_BYTES>>>(qk, v);
    combine_kernel<<<(BB * SS * 16) / 256, 256>>>(out);
}